// round 1
// baseline (speedup 1.0000x reference)
#include <cuda_runtime.h>
#include <math.h>

#define BATCH 16
#define ENCN  64
#define HDIM  96
#define EDIM  128
#define VOC   32000

// ---------------- scratch (device globals: no allocation allowed) ----------------
__device__ float g_encfeat[BATCH * ENCN * HDIM];  // shared by both attn calls
__device__ float g_ctx1[BATCH * HDIM];
__device__ float g_cov1[BATCH * ENCN];
__device__ float g_hnew[BATCH * HDIM];
__device__ float g_o[BATCH * HDIM];
__device__ float g_logits[BATCH * VOC];
__device__ float g_psum[512 * BATCH];
__device__ float g_logZ[BATCH];

// =====================================================================
// K1: enc_feat[b,o,w] = attn_b[o] + sum_i sum_d enc[b,i,w+d-47] * attn_w[o,i,47,d]
// Only the kh=47 slice of attn_w is live (input height dim is 1).
// Block = (b, o-pair). smem: zero-padded E rows (64x192) + interleaved K pairs.
// 128 threads = 8 i-groups x 16 w-threads; each thread: 6 contiguous w,
// rotating 6-register sliding window over E.
// =====================================================================
extern __shared__ float smem1[];

__global__ void enc_feat_kernel(const float* __restrict__ enc,
                                const float* __restrict__ attn_w,
                                const float* __restrict__ attn_b) {
    int b  = blockIdx.x >> 5;       // 16 batches
    int gp = blockIdx.x & 31;       // 32 o-pairs
    int o0 = gp * 2;

    float*  sE = smem1;                         // 64 * 192 floats (zero padded)
    float2* sK = (float2*)(smem1 + 64 * 192);   // 64 * 96 float2 (o0,o1 interleaved)
    int tid = threadIdx.x;          // 128

    // zero padded E
    float4* sE4 = (float4*)sE;
    for (int i = tid; i < 64 * 192 / 4; i += 128) sE4[i] = make_float4(0.f, 0.f, 0.f, 0.f);
    __syncthreads();

    // fill E: sE[i][47 + x] = enc[b,i,x]
    const float* eb = enc + b * ENCN * HDIM;
    for (int idx = tid; idx < ENCN * HDIM; idx += 128) {
        int i = idx / 96;
        int x = idx - i * 96;
        sE[i * 192 + 47 + x] = eb[idx];
    }
    // fill K pairs: attn_w[o,i,47,d] at offset o*589824 + i*9216 + 47*96 + d
    const float* k0 = attn_w + (size_t)o0 * 589824 + 4512;
    const float* k1 = k0 + 589824;
    for (int idx = tid; idx < 64 * 96; idx += 128) {
        int i = idx / 96;
        int d = idx - i * 96;
        sK[idx] = make_float2(k0[i * 9216 + d], k1[i * 9216 + d]);
    }
    __syncthreads();

    int ig = tid >> 4;      // i-group 0..7 (8 channels each)
    int wt = tid & 15;      // w-tile 0..15
    int w0 = wt * 6;

    float a0[6] = {0.f, 0.f, 0.f, 0.f, 0.f, 0.f};
    float a1[6] = {0.f, 0.f, 0.f, 0.f, 0.f, 0.f};

#pragma unroll 1
    for (int i = ig * 8; i < ig * 8 + 8; i++) {
        const float*  Er = sE + i * 192 + w0;
        const float2* Kr = sK + i * 96;
        float e[6];
#pragma unroll
        for (int j = 0; j < 6; j++) e[j] = Er[j];
#pragma unroll 1
        for (int d = 0; d < 96; d += 6) {
#pragma unroll
            for (int u = 0; u < 6; u++) {
                float2 k = Kr[d + u];
#pragma unroll
                for (int j = 0; j < 6; j++) {
                    float ev = e[(u + j) % 6];   // static after unroll
                    a0[j] = fmaf(ev, k.x, a0[j]);
                    a1[j] = fmaf(ev, k.y, a1[j]);
                }
                e[u] = Er[d + u + 6];            // slide window (max idx 101 <= 191-w0)
            }
        }
    }

    // reduce the 8 i-groups
    __syncthreads();
    float* red = smem1;     // reuse
#pragma unroll
    for (int j = 0; j < 6; j++) {
        red[tid * 12 + j]     = a0[j];
        red[tid * 12 + 6 + j] = a1[j];
    }
    __syncthreads();
    for (int s = 64; s >= 16; s >>= 1) {
        if (tid < s) {
#pragma unroll
            for (int j = 0; j < 12; j++) red[tid * 12 + j] += red[(tid + s) * 12 + j];
        }
        __syncthreads();
    }
    if (tid < 16) {
        float bb0 = attn_b[o0];
        float bb1 = attn_b[o0 + 1];
#pragma unroll
        for (int j = 0; j < 6; j++) {
            g_encfeat[(b * ENCN + o0) * 96 + tid * 6 + j]     = red[tid * 12 + j] + bb0;
            g_encfeat[(b * ENCN + o0 + 1) * 96 + tid * 6 + j] = red[tid * 12 + 6 + j] + bb1;
        }
    }
}

// =====================================================================
// K2/K4: attention tail. phase 0: hidden/coverage from inputs, ctx->g_ctx1,
// cov->g_cov1. phase 1: hidden=g_hnew, coverage=g_cov1, outputs to out buffer.
// =====================================================================
__global__ void attn_tail_kernel(const float* __restrict__ enc,
                                 const float* __restrict__ hidden_ext,
                                 const float* __restrict__ cov_ext,
                                 const float* __restrict__ W_dec,
                                 const float* __restrict__ b_dec,
                                 const float* __restrict__ cvg_w,
                                 const float* __restrict__ cvg_b,
                                 const float* __restrict__ v,
                                 float* ctx_ext, float* cov_out_ext, float* aw_ext,
                                 int phase) {
    int b = blockIdx.x;
    int t = threadIdx.x;    // 96

    const float* hid    = phase ? (const float*)g_hnew : hidden_ext;
    const float* cov_in = phase ? (const float*)g_cov1 : cov_ext;
    float* ctx_out = phase ? ctx_ext : g_ctx1;
    float* cov_out = phase ? cov_out_ext : g_cov1;
    float* aw_out  = phase ? aw_ext : nullptr;

    __shared__ float sh[96], sdec[96], scvg[64], ss[64], sv[96], saw[64];
    sh[t] = hid[b * 96 + t];
    sv[t] = v[b * 96 + t];
    __syncthreads();

    // dec_feat[h] = hidden . W_dec[h,:] + b_dec[h]
    {
        float a = b_dec[t];
        const float* wr = W_dec + t * 96;
#pragma unroll 4
        for (int j = 0; j < 96; j++) a = fmaf(sh[j], wr[j], a);
        sdec[t] = a;
    }
    // cvg_feat[e] = sum_i cov[i] * cvg_w[e,i,0,47] + cvg_b[e]
    if (t < 64) {
        float c = cvg_b[t];
        const float* cw = cvg_w + t * 6144 + 47;
        const float* cv = cov_in + b * 64;
#pragma unroll 4
        for (int i = 0; i < 64; i++) c = fmaf(cv[i], cw[i * 96], c);
        scvg[t] = c;
    }
    __syncthreads();

    // scores[e] = sum_h tanh(ef + dec + cvg) * v[h]
    if (t < 64) {
        const float* ef = g_encfeat + (b * 64 + t) * 96;
        float cg = scvg[t];
        float s = 0.f;
        for (int h = 0; h < 96; h++) s = fmaf(tanhf(ef[h] + sdec[h] + cg), sv[h], s);
        ss[t] = s;
    }
    __syncthreads();

    // softmax over ENC=64 (each thread redundantly, deterministic)
    float m = -1e30f;
    for (int e = 0; e < 64; e++) m = fmaxf(m, ss[e]);
    float Z = 0.f;
    for (int e = 0; e < 64; e++) Z += expf(ss[e] - m);
    float invZ = 1.0f / Z;
    if (t < 64) {
        float aw = expf(ss[t] - m) * invZ;
        saw[t] = aw;
        cov_out[b * 64 + t] = cov_in[b * 64 + t] + aw;
        if (aw_out) aw_out[b * 64 + t] = aw;
    }
    __syncthreads();

    // ctx[h] = sum_e aw[e] * enc[b,e,h]
    {
        float c = 0.f;
        const float* eb = enc + b * ENCN * HDIM + t;
#pragma unroll 4
        for (int e = 0; e < 64; e++) c = fmaf(saw[e], eb[e * 96], c);
        ctx_out[b * 96 + t] = c;
    }
}

// =====================================================================
// K3: x = cat(emb[id], ctx1) @ W_new.T + b_new ; one GRU step -> h_new
// =====================================================================
__global__ void gru_kernel(const int* __restrict__ ids,
                           const float* __restrict__ hidden,
                           const float* __restrict__ emb,
                           const float* __restrict__ W_new,
                           const float* __restrict__ b_new,
                           const float* __restrict__ w_ih,
                           const float* __restrict__ w_hh,
                           const float* __restrict__ b_ih,
                           const float* __restrict__ b_hh,
                           float* __restrict__ out_hidden) {
    int b = blockIdx.x;
    int t = threadIdx.x;    // 96
    __shared__ float scat[224], sx[96], shold[96];

    int id = ids[b];
    for (int k = t; k < 224; k += 96)
        scat[k] = (k < 128) ? emb[(size_t)id * 128 + k] : g_ctx1[b * 96 + (k - 128)];
    shold[t] = hidden[b * 96 + t];
    __syncthreads();

    {
        float x = b_new[t];
        const float* wr = W_new + t * 224;
#pragma unroll 4
        for (int k = 0; k < 224; k++) x = fmaf(scat[k], wr[k], x);
        sx[t] = x;
    }
    __syncthreads();

    float gir = b_ih[t], giz = b_ih[96 + t], gin = b_ih[192 + t];
    float ghr = b_hh[t], ghz = b_hh[96 + t], ghn = b_hh[192 + t];
    const float* wi0 = w_ih + t * 96;
    const float* wi1 = w_ih + (96 + t) * 96;
    const float* wi2 = w_ih + (192 + t) * 96;
    const float* wh0 = w_hh + t * 96;
    const float* wh1 = w_hh + (96 + t) * 96;
    const float* wh2 = w_hh + (192 + t) * 96;
#pragma unroll 4
    for (int j = 0; j < 96; j++) {
        float xv = sx[j], hv = shold[j];
        gir = fmaf(xv, wi0[j], gir);
        giz = fmaf(xv, wi1[j], giz);
        gin = fmaf(xv, wi2[j], gin);
        ghr = fmaf(hv, wh0[j], ghr);
        ghz = fmaf(hv, wh1[j], ghz);
        ghn = fmaf(hv, wh2[j], ghn);
    }
    float r = 1.0f / (1.0f + expf(-(gir + ghr)));
    float z = 1.0f / (1.0f + expf(-(giz + ghz)));
    float n = tanhf(gin + r * ghn);
    float hn = (1.0f - z) * n + z * shold[t];
    g_hnew[b * 96 + t] = hn;
    out_hidden[b * 96 + t] = hn;
}

// =====================================================================
// K5: o = tanh(cat(h_new, ctx2) @ W_pre.T + b_pre)
// =====================================================================
__global__ void outproj_kernel(const float* __restrict__ W_pre,
                               const float* __restrict__ b_pre,
                               const float* __restrict__ ctx2) {
    int b = blockIdx.x;
    int t = threadIdx.x;    // 96
    __shared__ float sc[192];
    sc[t] = g_hnew[b * 96 + t];
    sc[96 + t] = ctx2[b * 96 + t];
    __syncthreads();
    float a = b_pre[t];
    const float* wr = W_pre + t * 192;
#pragma unroll 4
    for (int k = 0; k < 192; k++) a = fmaf(sc[k], wr[k], a);
    g_o[b * 96 + t] = tanhf(a);
}

// =====================================================================
// K6: logits[b,v] = o[b] . W_out[v] + b_out[v]; per-block deterministic
// sumexp partials (logits bounded: no max shift needed, but tree reduce
// keeps it bit-deterministic).
// =====================================================================
__global__ void logits_kernel(const float* __restrict__ W_out,
                              const float* __restrict__ b_out) {
    __shared__ float sW[64 * 97];                 // padded: stride 97 kills bank conflicts
    __shared__ __align__(16) float sO[96 * 16];   // [k][b]
    __shared__ float red[64 * 17];
    int t = threadIdx.x;        // 64
    int v0 = blockIdx.x * 64;

    for (int idx = t; idx < 64 * 96; idx += 64) {
        int r = idx / 96;
        int k = idx - r * 96;
        sW[r * 97 + k] = W_out[(size_t)v0 * 96 + idx];
    }
    for (int idx = t; idx < 1536; idx += 64) {
        int k = idx >> 4, bb = idx & 15;
        sO[idx] = g_o[bb * 96 + k];
    }
    __syncthreads();

    float acc[16];
    float bo = b_out[v0 + t];
#pragma unroll
    for (int bb = 0; bb < 16; bb++) acc[bb] = bo;

    const float* wr = sW + t * 97;
#pragma unroll 4
    for (int k = 0; k < 96; k++) {
        float w = wr[k];
        const float4* o4 = (const float4*)(sO + k * 16);
#pragma unroll
        for (int q = 0; q < 4; q++) {
            float4 ov = o4[q];
            acc[q * 4 + 0] = fmaf(w, ov.x, acc[q * 4 + 0]);
            acc[q * 4 + 1] = fmaf(w, ov.y, acc[q * 4 + 1]);
            acc[q * 4 + 2] = fmaf(w, ov.z, acc[q * 4 + 2]);
            acc[q * 4 + 3] = fmaf(w, ov.w, acc[q * 4 + 3]);
        }
    }
#pragma unroll
    for (int bb = 0; bb < 16; bb++) {
        g_logits[bb * VOC + v0 + t] = acc[bb];
        red[t * 17 + bb] = expf(acc[bb]);
    }
    __syncthreads();
    for (int s = 32; s >= 1; s >>= 1) {
        if (t < s) {
#pragma unroll
            for (int bb = 0; bb < 16; bb++) red[t * 17 + bb] += red[(t + s) * 17 + bb];
        }
        __syncthreads();
    }
    if (t == 0) {
#pragma unroll
        for (int bb = 0; bb < 16; bb++) g_psum[blockIdx.x * 16 + bb] = red[bb];
    }
}

__global__ void reduce_kernel() {
    int t = threadIdx.x;
    if (t < 16) {
        float s = 0.f;
        for (int blk = 0; blk < VOC / 64; blk++) s += g_psum[blk * 16 + t];
        g_logZ[t] = logf(s);
    }
}

__global__ void writelogp_kernel(float* __restrict__ out) {
    int idx = blockIdx.x * 256 + threadIdx.x;
    if (idx < BATCH * VOC) {
        int b = idx / VOC;
        out[idx] = g_logits[idx] - g_logZ[b];
    }
}

// =====================================================================
extern "C" void kernel_launch(void* const* d_in, const int* in_sizes, int n_in,
                              void* d_out, int out_size) {
    const float* enc      = (const float*)d_in[0];
    const int*   ids      = (const int*)d_in[1];
    const float* hidden   = (const float*)d_in[2];
    const float* coverage = (const float*)d_in[3];
    const float* emb      = (const float*)d_in[4];
    const float* W_dec    = (const float*)d_in[5];
    const float* b_dec    = (const float*)d_in[6];
    const float* attn_w   = (const float*)d_in[7];
    const float* attn_b   = (const float*)d_in[8];
    const float* cvg_w    = (const float*)d_in[9];
    const float* cvg_b    = (const float*)d_in[10];
    const float* v        = (const float*)d_in[11];
    const float* W_new    = (const float*)d_in[12];
    const float* b_new    = (const float*)d_in[13];
    const float* w_ih     = (const float*)d_in[14];
    const float* w_hh     = (const float*)d_in[15];
    const float* b_ih     = (const float*)d_in[16];
    const float* b_hh     = (const float*)d_in[17];
    const float* W_pre    = (const float*)d_in[18];
    const float* b_pre    = (const float*)d_in[19];
    const float* W_out    = (const float*)d_in[20];
    const float* b_out    = (const float*)d_in[21];

    float* out        = (float*)d_out;
    float* out_logp   = out;                       // 16*32000
    float* out_hidden = out + 512000;              // 1*16*96
    float* out_ctx2   = out + 513536;              // 16*96
    float* out_aw2    = out + 515072;              // 16*64
    float* out_cov2   = out + 516096;              // 16*64

    cudaFuncSetAttribute(enc_feat_kernel, cudaFuncAttributeMaxDynamicSharedMemorySize, 98304);

    // K1: shared enc_feat (used by both attention calls)
    enc_feat_kernel<<<512, 128, 98304>>>(enc, attn_w, attn_b);
    // K2: attention #1
    attn_tail_kernel<<<16, 96>>>(enc, hidden, coverage, W_dec, b_dec, cvg_w, cvg_b, v,
                                 nullptr, nullptr, nullptr, 0);
    // K3: embedding + W_new + GRU step
    gru_kernel<<<16, 96>>>(ids, hidden, emb, W_new, b_new, w_ih, w_hh, b_ih, b_hh, out_hidden);
    // K4: attention #2 (writes ctx2/aw2/cov2 outputs)
    attn_tail_kernel<<<16, 96>>>(enc, nullptr, nullptr, W_dec, b_dec, cvg_w, cvg_b, v,
                                 out_ctx2, out_cov2, out_aw2, 1);
    // K5: o = tanh(W_pre @ cat(h_new, ctx2))
    outproj_kernel<<<16, 96>>>(W_pre, b_pre, out_ctx2);
    // K6..K8: output projection + deterministic log_softmax
    logits_kernel<<<VOC / 64, 64>>>(W_out, b_out);
    reduce_kernel<<<1, 32>>>();
    writelogp_kernel<<<(BATCH * VOC + 255) / 256, 256>>>(out_logp);
}

// round 2
// speedup vs baseline: 1.2787x; 1.2787x over previous
#include <cuda_runtime.h>
#include <math.h>

#define BATCH 16
#define ENCN  64
#define HDIM  96
#define EDIM  128
#define VOC   32000

typedef unsigned long long u64;

__device__ __forceinline__ u64 pack2(float x) {
    u64 r;
    asm("mov.b64 %0, {%1, %1};" : "=l"(r) : "r"(__float_as_uint(x)));
    return r;
}
__device__ __forceinline__ u64 fma2(u64 a, u64 b, u64 c) {
    u64 d;
    asm("fma.rn.f32x2 %0, %1, %2, %3;" : "=l"(d) : "l"(a), "l"(b), "l"(c));
    return d;
}
__device__ __forceinline__ void unpack2(u64 v, float& lo, float& hi) {
    unsigned int l, h;
    asm("mov.b64 {%0, %1}, %2;" : "=r"(l), "=r"(h) : "l"(v));
    lo = __uint_as_float(l);
    hi = __uint_as_float(h);
}

// ---------------- scratch (device globals: no allocation allowed) ----------------
__device__ float g_encfeat[BATCH * ENCN * HDIM];  // shared by both attn calls
__device__ float g_ctx1[BATCH * HDIM];
__device__ float g_cov1[BATCH * ENCN];
__device__ float g_hnew[BATCH * HDIM];
__device__ float g_o[BATCH * HDIM];
__device__ float g_logits[BATCH * VOC];
__device__ float g_psum[512 * BATCH];
__device__ float g_logZ[BATCH];

// =====================================================================
// K1: enc_feat[b,o,w] = attn_b[o] + sum_i sum_d enc[b,i,w+d-47] * attn_w[o,i,47,d]
// Only the kh=47 slice of attn_w is live (input height dim is 1).
// Block = (b, o-pair). smem: zero-padded E rows (64x192) + interleaved K pairs.
// 128 threads = 8 i-groups x 16 w-threads; each thread: 6 contiguous w,
// rotating packed (e,e) window; inner loop = 6x fma.rn.f32x2 per u-step.
// =====================================================================
extern __shared__ float smem1[];

__global__ void enc_feat_kernel(const float* __restrict__ enc,
                                const float* __restrict__ attn_w,
                                const float* __restrict__ attn_b) {
    int b  = blockIdx.x >> 5;       // 16 batches
    int gp = blockIdx.x & 31;       // 32 o-pairs
    int o0 = gp * 2;

    float* sE = smem1;                        // 64 * 192 floats (zero padded)
    u64*   sK = (u64*)(smem1 + 64 * 192);     // 64 * 96 packed (k_o0, k_o1)
    int tid = threadIdx.x;          // 128

    // zero padded E
    float4* sE4 = (float4*)sE;
    for (int i = tid; i < 64 * 192 / 4; i += 128) sE4[i] = make_float4(0.f, 0.f, 0.f, 0.f);
    __syncthreads();

    // fill E: sE[i][47 + x] = enc[b,i,x]
    const float* eb = enc + b * ENCN * HDIM;
    for (int idx = tid; idx < ENCN * HDIM; idx += 128) {
        int i = idx / 96;
        int x = idx - i * 96;
        sE[i * 192 + 47 + x] = eb[idx];
    }
    // fill K pairs: attn_w[o,i,47,d] at offset o*589824 + i*9216 + 47*96 + d
    const float* k0 = attn_w + (size_t)o0 * 589824 + 4512;
    const float* k1 = k0 + 589824;
    for (int idx = tid; idx < 64 * 96; idx += 128) {
        int i = idx / 96;
        int d = idx - i * 96;
        float2 kk = make_float2(k0[i * 9216 + d], k1[i * 9216 + d]);
        sK[idx] = *(u64*)&kk;
    }
    __syncthreads();

    int ig = tid >> 4;      // i-group 0..7 (8 channels each)
    int wt = tid & 15;      // w-tile 0..15
    int w0 = wt * 6;

    u64 acc[6] = {0ull, 0ull, 0ull, 0ull, 0ull, 0ull};

#pragma unroll 1
    for (int i = ig * 8; i < ig * 8 + 8; i++) {
        const float* Er = sE + i * 192 + w0;
        const u64*   Kr = sK + i * 96;
        u64 ep[6];
#pragma unroll
        for (int j = 0; j < 6; j++) ep[j] = pack2(Er[j]);
#pragma unroll 1
        for (int d = 0; d < 96; d += 6) {
#pragma unroll
            for (int u = 0; u < 6; u++) {
                u64 k2 = Kr[d + u];
#pragma unroll
                for (int j = 0; j < 6; j++) {
                    acc[j] = fma2(ep[(u + j) % 6], k2, acc[j]);  // static idx after unroll
                }
                ep[u] = pack2(Er[d + u + 6]);    // slide window (max idx 101 <= 191-w0)
            }
        }
    }

    float a0[6], a1[6];
#pragma unroll
    for (int j = 0; j < 6; j++) unpack2(acc[j], a0[j], a1[j]);

    // reduce the 8 i-groups
    __syncthreads();
    float* red = smem1;     // reuse
#pragma unroll
    for (int j = 0; j < 6; j++) {
        red[tid * 12 + j]     = a0[j];
        red[tid * 12 + 6 + j] = a1[j];
    }
    __syncthreads();
    for (int s = 64; s >= 16; s >>= 1) {
        if (tid < s) {
#pragma unroll
            for (int j = 0; j < 12; j++) red[tid * 12 + j] += red[(tid + s) * 12 + j];
        }
        __syncthreads();
    }
    if (tid < 16) {
        float bb0 = attn_b[o0];
        float bb1 = attn_b[o0 + 1];
#pragma unroll
        for (int j = 0; j < 6; j++) {
            g_encfeat[(b * ENCN + o0) * 96 + tid * 6 + j]     = red[tid * 12 + j] + bb0;
            g_encfeat[(b * ENCN + o0 + 1) * 96 + tid * 6 + j] = red[tid * 12 + 6 + j] + bb1;
        }
    }
}

// =====================================================================
// K2/K4: attention tail, warp-per-output-row. block = 1024 (32 warps).
// phase 0: hidden/coverage from inputs, ctx->g_ctx1, cov->g_cov1.
// phase 1: hidden=g_hnew, coverage=g_cov1, outputs to out buffers.
// =====================================================================
__global__ void attn_tail_kernel(const float* __restrict__ enc,
                                 const float* __restrict__ hidden_ext,
                                 const float* __restrict__ cov_ext,
                                 const float* __restrict__ W_dec,
                                 const float* __restrict__ b_dec,
                                 const float* __restrict__ cvg_w,
                                 const float* __restrict__ cvg_b,
                                 const float* __restrict__ v,
                                 float* ctx_ext, float* cov_out_ext, float* aw_ext,
                                 int phase) {
    int b    = blockIdx.x;
    int t    = threadIdx.x;     // 1024
    int warp = t >> 5;          // 32 warps
    int lane = t & 31;

    const float* hid    = phase ? (const float*)g_hnew : hidden_ext;
    const float* cov_in = phase ? (const float*)g_cov1 : cov_ext;
    float* ctx_out = phase ? ctx_ext : g_ctx1;
    float* cov_out = phase ? cov_out_ext : g_cov1;
    float* aw_out  = phase ? aw_ext : nullptr;

    __shared__ float sh[96], sv[96], sdec[96], scvg[64], ss[64], sred[64], saw[64], scov[64];

    if (t < 96) { sh[t] = hid[b * 96 + t]; sv[t] = v[b * 96 + t]; }
    if (t < 64) scov[t] = cov_in[b * 64 + t];
    __syncthreads();

    // dec_feat: warp w -> rows h = 3w..3w+2 of W_dec (coalesced lane loads)
    {
#pragma unroll
        for (int k = 0; k < 3; k++) {
            int h = warp * 3 + k;
            const float* wr = W_dec + h * 96;
            float a = sh[lane] * wr[lane];
            a = fmaf(sh[lane + 32], wr[lane + 32], a);
            a = fmaf(sh[lane + 64], wr[lane + 64], a);
#pragma unroll
            for (int s = 16; s > 0; s >>= 1) a += __shfl_down_sync(0xffffffffu, a, s);
            if (lane == 0) sdec[h] = a + b_dec[h];
        }
    }
    // cvg_feat: warp w -> rows e = 2w, 2w+1 (column 47 of cvg_w, stride 96)
    {
#pragma unroll
        for (int k = 0; k < 2; k++) {
            int e = warp * 2 + k;
            const float* cw = cvg_w + e * 6144 + 47;
            float c = scov[lane] * cw[lane * 96];
            c = fmaf(scov[lane + 32], cw[(lane + 32) * 96], c);
#pragma unroll
            for (int s = 16; s > 0; s >>= 1) c += __shfl_down_sync(0xffffffffu, c, s);
            if (lane == 0) scvg[e] = c + cvg_b[e];
        }
    }
    __syncthreads();

    // scores: warp w -> e = 2w, 2w+1
    {
#pragma unroll
        for (int k = 0; k < 2; k++) {
            int e = warp * 2 + k;
            const float* ef = g_encfeat + (b * 64 + e) * 96;
            float cg = scvg[e];
            float a = 0.f;
#pragma unroll
            for (int q = 0; q < 3; q++) {
                int h = lane + 32 * q;
                a = fmaf(tanhf(ef[h] + sdec[h] + cg), sv[h], a);
            }
#pragma unroll
            for (int s = 16; s > 0; s >>= 1) a += __shfl_down_sync(0xffffffffu, a, s);
            if (lane == 0) ss[e] = a;
        }
    }
    __syncthreads();

    // softmax over ENC=64, deterministic fixed-order reductions
    float ex = 0.f;
    if (t < 64) {
        float m = -1e30f;
#pragma unroll
        for (int e = 0; e < 64; e++) m = fmaxf(m, ss[e]);
        ex = expf(ss[t] - m);
        sred[t] = ex;
    }
    __syncthreads();
    for (int s = 32; s >= 1; s >>= 1) {
        if (t < s) sred[t] += sred[t + s];
        __syncthreads();
    }
    float invZ = 1.0f / sred[0];
    if (t < 64) {
        float aw = ex * invZ;
        saw[t] = aw;
        cov_out[b * 64 + t] = scov[t] + aw;
        if (aw_out) aw_out[b * 64 + t] = aw;
    }
    __syncthreads();

    // ctx[h] = sum_e aw[e] * enc[b,e,h]  (coalesced across t)
    if (t < 96) {
        float c = 0.f;
        const float* ebp = enc + b * ENCN * HDIM + t;
#pragma unroll 8
        for (int e = 0; e < 64; e++) c = fmaf(saw[e], ebp[e * 96], c);
        ctx_out[b * 96 + t] = c;
    }
}

// =====================================================================
// K3: x = cat(emb[id], ctx1) @ W_new.T + b_new ; one GRU step -> h_new
// warp-per-row, block = 1024.
// =====================================================================
__global__ void gru_kernel(const int* __restrict__ ids,
                           const float* __restrict__ hidden,
                           const float* __restrict__ emb,
                           const float* __restrict__ W_new,
                           const float* __restrict__ b_new,
                           const float* __restrict__ w_ih,
                           const float* __restrict__ w_hh,
                           const float* __restrict__ b_ih,
                           const float* __restrict__ b_hh,
                           float* __restrict__ out_hidden) {
    int b    = blockIdx.x;
    int t    = threadIdx.x;     // 1024
    int warp = t >> 5;
    int lane = t & 31;
    __shared__ float scat[224], shold[96], sx[96], sgi[288], sgh[288];

    int id = ids[b];
    if (t < 224) scat[t] = (t < 128) ? emb[(size_t)id * 128 + t] : g_ctx1[b * 96 + (t - 128)];
    if (t < 96)  shold[t] = hidden[b * 96 + t];
    __syncthreads();

    // x[h] = scat . W_new[h,:] + b_new[h]   (96 rows of 224, warp -> 3 rows)
#pragma unroll
    for (int k = 0; k < 3; k++) {
        int h = warp * 3 + k;
        const float* wr = W_new + h * 224;
        float a = 0.f;
#pragma unroll
        for (int q = 0; q < 7; q++) {
            int j = lane + 32 * q;
            a = fmaf(scat[j], wr[j], a);
        }
#pragma unroll
        for (int s = 16; s > 0; s >>= 1) a += __shfl_down_sync(0xffffffffu, a, s);
        if (lane == 0) sx[h] = a + b_new[h];
    }
    __syncthreads();

    // 576 gate rows (288 gi from w_ih @ x, 288 gh from w_hh @ h): warp -> 18 rows
#pragma unroll
    for (int k = 0; k < 18; k++) {
        int r = k * 32 + warp;          // 0..575
        bool is_gi = r < 288;
        int rr = is_gi ? r : r - 288;
        const float* wr  = (is_gi ? w_ih : w_hh) + rr * 96;
        const float* vec = is_gi ? sx : shold;
        float a = vec[lane] * wr[lane];
        a = fmaf(vec[lane + 32], wr[lane + 32], a);
        a = fmaf(vec[lane + 64], wr[lane + 64], a);
#pragma unroll
        for (int s = 16; s > 0; s >>= 1) a += __shfl_down_sync(0xffffffffu, a, s);
        if (lane == 0) {
            if (is_gi) sgi[rr] = a + b_ih[rr];
            else       sgh[rr] = a + b_hh[rr];
        }
    }
    __syncthreads();

    if (t < 96) {
        float r = 1.0f / (1.0f + expf(-(sgi[t] + sgh[t])));
        float z = 1.0f / (1.0f + expf(-(sgi[96 + t] + sgh[96 + t])));
        float n = tanhf(sgi[192 + t] + r * sgh[192 + t]);
        float hn = (1.0f - z) * n + z * shold[t];
        g_hnew[b * 96 + t] = hn;
        out_hidden[b * 96 + t] = hn;
    }
}

// =====================================================================
// K5: o = tanh(cat(h_new, ctx2) @ W_pre.T + b_pre)   warp-per-row
// =====================================================================
__global__ void outproj_kernel(const float* __restrict__ W_pre,
                               const float* __restrict__ b_pre,
                               const float* __restrict__ ctx2) {
    int b    = blockIdx.x;
    int t    = threadIdx.x;   // 1024
    int warp = t >> 5;
    int lane = t & 31;
    __shared__ float sc[192];
    if (t < 96) { sc[t] = g_hnew[b * 96 + t]; sc[96 + t] = ctx2[b * 96 + t]; }
    __syncthreads();
#pragma unroll
    for (int k = 0; k < 3; k++) {
        int h = warp * 3 + k;
        const float* wr = W_pre + h * 192;
        float a = 0.f;
#pragma unroll
        for (int q = 0; q < 6; q++) {
            int j = lane + 32 * q;
            a = fmaf(sc[j], wr[j], a);
        }
#pragma unroll
        for (int s = 16; s > 0; s >>= 1) a += __shfl_down_sync(0xffffffffu, a, s);
        if (lane == 0) g_o[b * 96 + h] = tanhf(a + b_pre[h]);
    }
}

// =====================================================================
// K6: logits[b,v] = o[b] . W_out[v] + b_out[v]; per-block deterministic
// sumexp partials.
// =====================================================================
__global__ void logits_kernel(const float* __restrict__ W_out,
                              const float* __restrict__ b_out) {
    __shared__ float sW[64 * 97];                 // padded: stride 97 kills bank conflicts
    __shared__ __align__(16) float sO[96 * 16];   // [k][b]
    __shared__ float red[64 * 17];
    int t = threadIdx.x;        // 64
    int v0 = blockIdx.x * 64;

    for (int idx = t; idx < 64 * 96; idx += 64) {
        int r = idx / 96;
        int k = idx - r * 96;
        sW[r * 97 + k] = W_out[(size_t)v0 * 96 + idx];
    }
    for (int idx = t; idx < 1536; idx += 64) {
        int k = idx >> 4, bb = idx & 15;
        sO[idx] = g_o[bb * 96 + k];
    }
    __syncthreads();

    float acc[16];
    float bo = b_out[v0 + t];
#pragma unroll
    for (int bb = 0; bb < 16; bb++) acc[bb] = bo;

    const float* wr = sW + t * 97;
#pragma unroll 4
    for (int k = 0; k < 96; k++) {
        float w = wr[k];
        const float4* o4 = (const float4*)(sO + k * 16);
#pragma unroll
        for (int q = 0; q < 4; q++) {
            float4 ov = o4[q];
            acc[q * 4 + 0] = fmaf(w, ov.x, acc[q * 4 + 0]);
            acc[q * 4 + 1] = fmaf(w, ov.y, acc[q * 4 + 1]);
            acc[q * 4 + 2] = fmaf(w, ov.z, acc[q * 4 + 2]);
            acc[q * 4 + 3] = fmaf(w, ov.w, acc[q * 4 + 3]);
        }
    }
#pragma unroll
    for (int bb = 0; bb < 16; bb++) {
        g_logits[bb * VOC + v0 + t] = acc[bb];
        red[t * 17 + bb] = expf(acc[bb]);
    }
    __syncthreads();
    for (int s = 32; s >= 1; s >>= 1) {
        if (t < s) {
#pragma unroll
            for (int bb = 0; bb < 16; bb++) red[t * 17 + bb] += red[(t + s) * 17 + bb];
        }
        __syncthreads();
    }
    if (t == 0) {
#pragma unroll
        for (int bb = 0; bb < 16; bb++) g_psum[blockIdx.x * 16 + bb] = red[bb];
    }
}

__global__ void reduce_kernel() {
    int t = threadIdx.x;
    if (t < 16) {
        float s = 0.f;
        for (int blk = 0; blk < VOC / 64; blk++) s += g_psum[blk * 16 + t];
        g_logZ[t] = logf(s);
    }
}

__global__ void writelogp_kernel(float* __restrict__ out) {
    int idx = blockIdx.x * 256 + threadIdx.x;
    if (idx < BATCH * VOC) {
        int b = idx / VOC;
        out[idx] = g_logits[idx] - g_logZ[b];
    }
}

// =====================================================================
extern "C" void kernel_launch(void* const* d_in, const int* in_sizes, int n_in,
                              void* d_out, int out_size) {
    const float* enc      = (const float*)d_in[0];
    const int*   ids      = (const int*)d_in[1];
    const float* hidden   = (const float*)d_in[2];
    const float* coverage = (const float*)d_in[3];
    const float* emb      = (const float*)d_in[4];
    const float* W_dec    = (const float*)d_in[5];
    const float* b_dec    = (const float*)d_in[6];
    const float* attn_w   = (const float*)d_in[7];
    const float* attn_b   = (const float*)d_in[8];
    const float* cvg_w    = (const float*)d_in[9];
    const float* cvg_b    = (const float*)d_in[10];
    const float* v        = (const float*)d_in[11];
    const float* W_new    = (const float*)d_in[12];
    const float* b_new    = (const float*)d_in[13];
    const float* w_ih     = (const float*)d_in[14];
    const float* w_hh     = (const float*)d_in[15];
    const float* b_ih     = (const float*)d_in[16];
    const float* b_hh     = (const float*)d_in[17];
    const float* W_pre    = (const float*)d_in[18];
    const float* b_pre    = (const float*)d_in[19];
    const float* W_out    = (const float*)d_in[20];
    const float* b_out    = (const float*)d_in[21];

    float* out        = (float*)d_out;
    float* out_logp   = out;                       // 16*32000
    float* out_hidden = out + 512000;              // 1*16*96
    float* out_ctx2   = out + 513536;              // 16*96
    float* out_aw2    = out + 515072;              // 16*64
    float* out_cov2   = out + 516096;              // 16*64

    cudaFuncSetAttribute(enc_feat_kernel, cudaFuncAttributeMaxDynamicSharedMemorySize, 98304);

    // K1: shared enc_feat (used by both attention calls)
    enc_feat_kernel<<<512, 128, 98304>>>(enc, attn_w, attn_b);
    // K2: attention #1
    attn_tail_kernel<<<16, 1024>>>(enc, hidden, coverage, W_dec, b_dec, cvg_w, cvg_b, v,
                                   nullptr, nullptr, nullptr, 0);
    // K3: embedding + W_new + GRU step
    gru_kernel<<<16, 1024>>>(ids, hidden, emb, W_new, b_new, w_ih, w_hh, b_ih, b_hh, out_hidden);
    // K4: attention #2 (writes ctx2/aw2/cov2 outputs)
    attn_tail_kernel<<<16, 1024>>>(enc, nullptr, nullptr, W_dec, b_dec, cvg_w, cvg_b, v,
                                   out_ctx2, out_cov2, out_aw2, 1);
    // K5: o = tanh(W_pre @ cat(h_new, ctx2))
    outproj_kernel<<<16, 1024>>>(W_pre, b_pre, out_ctx2);
    // K6..K8: output projection + deterministic log_softmax
    logits_kernel<<<VOC / 64, 64>>>(W_out, b_out);
    reduce_kernel<<<1, 32>>>();
    writelogp_kernel<<<(BATCH * VOC + 255) / 256, 256>>>(out_logp);
}

// round 3
// speedup vs baseline: 2.2229x; 1.7385x over previous
#include <cuda_runtime.h>
#include <math.h>

#define BATCH 16
#define ENCN  64
#define HDIM  96
#define EDIM  128
#define VOC   32000

typedef unsigned long long u64;

__device__ __forceinline__ u64 pack2(float x) {
    u64 r;
    asm("mov.b64 %0, {%1, %1};" : "=l"(r) : "r"(__float_as_uint(x)));
    return r;
}
__device__ __forceinline__ u64 fma2(u64 a, u64 b, u64 c) {
    u64 d;
    asm("fma.rn.f32x2 %0, %1, %2, %3;" : "=l"(d) : "l"(a), "l"(b), "l"(c));
    return d;
}
__device__ __forceinline__ void unpack2(u64 v, float& lo, float& hi) {
    unsigned int l, h;
    asm("mov.b64 {%0, %1}, %2;" : "=r"(l), "=r"(h) : "l"(v));
    lo = __uint_as_float(l);
    hi = __uint_as_float(h);
}

// ---------------- scratch ----------------
__device__ float g_encfeat[BATCH * ENCN * HDIM];
__device__ float g_o[BATCH * HDIM];
__device__ float g_psum[256 * BATCH];

// =====================================================================
// K1: enc_feat[b,o,w] = attn_b[o] + sum_i sum_d enc[b,i,w+d-47]*attn_w[o,i,47,d]
// =====================================================================
extern __shared__ float smem1[];

__global__ void enc_feat_kernel(const float* __restrict__ enc,
                                const float* __restrict__ attn_w,
                                const float* __restrict__ attn_b) {
    int b  = blockIdx.x >> 5;
    int gp = blockIdx.x & 31;
    int o0 = gp * 2;

    float* sE = smem1;                        // 64 * 192
    u64*   sK = (u64*)(smem1 + 64 * 192);     // 64 * 96 packed (k_o0, k_o1)
    int tid = threadIdx.x;          // 128

    float4* sE4 = (float4*)sE;
    for (int i = tid; i < 64 * 192 / 4; i += 128) sE4[i] = make_float4(0.f, 0.f, 0.f, 0.f);
    __syncthreads();

    const float* eb = enc + b * ENCN * HDIM;
    for (int idx = tid; idx < ENCN * HDIM; idx += 128) {
        int i = idx / 96;
        int x = idx - i * 96;
        sE[i * 192 + 47 + x] = eb[idx];
    }
    const float* k0 = attn_w + (size_t)o0 * 589824 + 4512;
    const float* k1 = k0 + 589824;
    for (int idx = tid; idx < 64 * 96; idx += 128) {
        int i = idx / 96;
        int d = idx - i * 96;
        float2 kk = make_float2(k0[i * 9216 + d], k1[i * 9216 + d]);
        sK[idx] = *(u64*)&kk;
    }
    __syncthreads();

    int ig = tid >> 4;
    int wt = tid & 15;
    int w0 = wt * 6;

    u64 acc[6] = {0ull, 0ull, 0ull, 0ull, 0ull, 0ull};

#pragma unroll 1
    for (int i = ig * 8; i < ig * 8 + 8; i++) {
        const float* Er = sE + i * 192 + w0;
        const u64*   Kr = sK + i * 96;
        u64 ep[6];
#pragma unroll
        for (int j = 0; j < 6; j++) ep[j] = pack2(Er[j]);
#pragma unroll 1
        for (int d = 0; d < 96; d += 6) {
#pragma unroll
            for (int u = 0; u < 6; u++) {
                u64 k2 = Kr[d + u];
#pragma unroll
                for (int j = 0; j < 6; j++) {
                    acc[j] = fma2(ep[(u + j) % 6], k2, acc[j]);
                }
                ep[u] = pack2(Er[d + u + 6]);
            }
        }
    }

    float a0[6], a1[6];
#pragma unroll
    for (int j = 0; j < 6; j++) unpack2(acc[j], a0[j], a1[j]);

    __syncthreads();
    float* red = smem1;
#pragma unroll
    for (int j = 0; j < 6; j++) {
        red[tid * 12 + j]     = a0[j];
        red[tid * 12 + 6 + j] = a1[j];
    }
    __syncthreads();
    for (int s = 64; s >= 16; s >>= 1) {
        if (tid < s) {
#pragma unroll
            for (int j = 0; j < 12; j++) red[tid * 12 + j] += red[(tid + s) * 12 + j];
        }
        __syncthreads();
    }
    if (tid < 16) {
        float bb0 = attn_b[o0];
        float bb1 = attn_b[o0 + 1];
#pragma unroll
        for (int j = 0; j < 6; j++) {
            g_encfeat[(b * ENCN + o0) * 96 + tid * 6 + j]     = red[tid * 12 + j] + bb0;
            g_encfeat[(b * ENCN + o0 + 1) * 96 + tid * 6 + j] = red[tid * 12 + 6 + j] + bb1;
        }
    }
}

// =====================================================================
// K2: fully fused per-batch decoder: attn1 -> GRU -> attn2 -> outproj.
// grid=16 (one block per batch), block=1024 (32 warps).
// Shared operands (W_dec, cvg col-47 gather, enc[b], encfeat[b]) cached
// in dynamic smem once, reused by both attention phases.
// =====================================================================
extern __shared__ float smem2[];

__global__ void decoder_fused_kernel(const float* __restrict__ enc,
                                     const int* __restrict__ ids,
                                     const float* __restrict__ hidden,
                                     const float* __restrict__ coverage,
                                     const float* __restrict__ emb,
                                     const float* __restrict__ W_dec,
                                     const float* __restrict__ b_dec,
                                     const float* __restrict__ cvg_w,
                                     const float* __restrict__ cvg_b,
                                     const float* __restrict__ v,
                                     const float* __restrict__ W_new,
                                     const float* __restrict__ b_new,
                                     const float* __restrict__ w_ih,
                                     const float* __restrict__ w_hh,
                                     const float* __restrict__ b_ih,
                                     const float* __restrict__ b_hh,
                                     const float* __restrict__ W_pre,
                                     const float* __restrict__ b_pre,
                                     float* __restrict__ out_hidden,
                                     float* __restrict__ out_ctx2,
                                     float* __restrict__ out_aw2,
                                     float* __restrict__ out_cov2) {
    int b    = blockIdx.x;
    int t    = threadIdx.x;     // 1024
    int warp = t >> 5;          // 0..31
    int lane = t & 31;

    // dynamic smem layout
    float* sWdec = smem2;               // 9216
    float* sC    = sWdec + 9216;        // 4096   C[e][i] = cvg_w[e,i,0,47]
    float* sEnc  = sC + 4096;           // 6144   enc[b]
    float* sEf   = sEnc + 6144;         // 6144   encfeat[b]

    __shared__ float sh[96], sv[96], scov[64], sdec[96], scvg[64], ss[64],
                     saw[64], sred[64], sctx[96], scat[224], sx[96],
                     sgi[288], sgh[288], shnew[96], so2[192];

    // ---- bulk loads ----
    for (int i = t; i < 9216; i += 1024) sWdec[i] = W_dec[i];
    for (int i = t; i < 4096; i += 1024) {
        int e = i >> 6, ii = i & 63;
        sC[i] = cvg_w[e * 6144 + ii * 96 + 47];
    }
    for (int i = t; i < 6144; i += 1024) {
        sEnc[i] = enc[b * 6144 + i];
        sEf[i]  = g_encfeat[b * 6144 + i];
    }
    if (t < 96) { sh[t] = hidden[b * 96 + t]; sv[t] = v[b * 96 + t]; }
    if (t < 64) scov[t] = coverage[b * 64 + t];
    __syncthreads();

    // =========== PHASE A: attention #1 ===========
#pragma unroll
    for (int k = 0; k < 3; k++) {
        int h = warp * 3 + k;
        const float* wr = sWdec + h * 96;
        float a = sh[lane] * wr[lane];
        a = fmaf(sh[lane + 32], wr[lane + 32], a);
        a = fmaf(sh[lane + 64], wr[lane + 64], a);
#pragma unroll
        for (int s = 16; s > 0; s >>= 1) a += __shfl_down_sync(0xffffffffu, a, s);
        if (lane == 0) sdec[h] = a + b_dec[h];
    }
#pragma unroll
    for (int k = 0; k < 2; k++) {
        int e = warp * 2 + k;
        const float* cw = sC + e * 64;
        float c = scov[lane] * cw[lane];
        c = fmaf(scov[lane + 32], cw[lane + 32], c);
#pragma unroll
        for (int s = 16; s > 0; s >>= 1) c += __shfl_down_sync(0xffffffffu, c, s);
        if (lane == 0) scvg[e] = c + cvg_b[e];
    }
    __syncthreads();

#pragma unroll
    for (int k = 0; k < 2; k++) {
        int e = warp * 2 + k;
        const float* ef = sEf + e * 96;
        float cg = scvg[e];
        float a = 0.f;
#pragma unroll
        for (int q = 0; q < 3; q++) {
            int h = lane + 32 * q;
            a = fmaf(tanhf(ef[h] + sdec[h] + cg), sv[h], a);
        }
#pragma unroll
        for (int s = 16; s > 0; s >>= 1) a += __shfl_down_sync(0xffffffffu, a, s);
        if (lane == 0) ss[e] = a;
    }
    __syncthreads();

    float ex = 0.f;
    if (t < 64) {
        float m = -1e30f;
#pragma unroll
        for (int e = 0; e < 64; e++) m = fmaxf(m, ss[e]);
        ex = expf(ss[t] - m);
        sred[t] = ex;
    }
    __syncthreads();
    for (int s = 32; s >= 1; s >>= 1) {
        if (t < s) sred[t] += sred[t + s];
        __syncthreads();
    }
    {
        float invZ = 1.0f / sred[0];
        if (t < 64) {
            float aw = ex * invZ;
            saw[t] = aw;
            scov[t] = scov[t] + aw;     // cov1, used by phase B
        }
    }
    __syncthreads();

    if (t < 96) {
        float c = 0.f;
        const float* ebp = sEnc + t;
#pragma unroll 8
        for (int e = 0; e < 64; e++) c = fmaf(saw[e], ebp[e * 96], c);
        sctx[t] = c;
    }
    __syncthreads();

    // =========== GRU ===========
    {
        int id = ids[b];
        if (t < 224) scat[t] = (t < 128) ? emb[(size_t)id * 128 + t] : sctx[t - 128];
    }
    __syncthreads();

#pragma unroll
    for (int k = 0; k < 3; k++) {
        int h = warp * 3 + k;
        const float* wr = W_new + h * 224;
        float a = 0.f;
#pragma unroll
        for (int q = 0; q < 7; q++) {
            int j = lane + 32 * q;
            a = fmaf(scat[j], wr[j], a);
        }
#pragma unroll
        for (int s = 16; s > 0; s >>= 1) a += __shfl_down_sync(0xffffffffu, a, s);
        if (lane == 0) sx[h] = a + b_new[h];
    }
    __syncthreads();

#pragma unroll
    for (int k = 0; k < 18; k++) {
        int r = k * 32 + warp;          // 0..575
        bool is_gi = r < 288;
        int rr = is_gi ? r : r - 288;
        const float* wr  = (is_gi ? w_ih : w_hh) + rr * 96;
        const float* vec = is_gi ? sx : sh;
        float a = vec[lane] * wr[lane];
        a = fmaf(vec[lane + 32], wr[lane + 32], a);
        a = fmaf(vec[lane + 64], wr[lane + 64], a);
#pragma unroll
        for (int s = 16; s > 0; s >>= 1) a += __shfl_down_sync(0xffffffffu, a, s);
        if (lane == 0) {
            if (is_gi) sgi[rr] = a + b_ih[rr];
            else       sgh[rr] = a + b_hh[rr];
        }
    }
    __syncthreads();

    if (t < 96) {
        float r = 1.0f / (1.0f + expf(-(sgi[t] + sgh[t])));
        float z = 1.0f / (1.0f + expf(-(sgi[96 + t] + sgh[96 + t])));
        float n = tanhf(sgi[192 + t] + r * sgh[192 + t]);
        float hn = (1.0f - z) * n + z * sh[t];
        shnew[t] = hn;
        out_hidden[b * 96 + t] = hn;
    }
    __syncthreads();

    // =========== PHASE B: attention #2 ===========
#pragma unroll
    for (int k = 0; k < 3; k++) {
        int h = warp * 3 + k;
        const float* wr = sWdec + h * 96;
        float a = shnew[lane] * wr[lane];
        a = fmaf(shnew[lane + 32], wr[lane + 32], a);
        a = fmaf(shnew[lane + 64], wr[lane + 64], a);
#pragma unroll
        for (int s = 16; s > 0; s >>= 1) a += __shfl_down_sync(0xffffffffu, a, s);
        if (lane == 0) sdec[h] = a + b_dec[h];
    }
#pragma unroll
    for (int k = 0; k < 2; k++) {
        int e = warp * 2 + k;
        const float* cw = sC + e * 64;
        float c = scov[lane] * cw[lane];
        c = fmaf(scov[lane + 32], cw[lane + 32], c);
#pragma unroll
        for (int s = 16; s > 0; s >>= 1) c += __shfl_down_sync(0xffffffffu, c, s);
        if (lane == 0) scvg[e] = c + cvg_b[e];
    }
    __syncthreads();

#pragma unroll
    for (int k = 0; k < 2; k++) {
        int e = warp * 2 + k;
        const float* ef = sEf + e * 96;
        float cg = scvg[e];
        float a = 0.f;
#pragma unroll
        for (int q = 0; q < 3; q++) {
            int h = lane + 32 * q;
            a = fmaf(tanhf(ef[h] + sdec[h] + cg), sv[h], a);
        }
#pragma unroll
        for (int s = 16; s > 0; s >>= 1) a += __shfl_down_sync(0xffffffffu, a, s);
        if (lane == 0) ss[e] = a;
    }
    __syncthreads();

    ex = 0.f;
    if (t < 64) {
        float m = -1e30f;
#pragma unroll
        for (int e = 0; e < 64; e++) m = fmaxf(m, ss[e]);
        ex = expf(ss[t] - m);
        sred[t] = ex;
    }
    __syncthreads();
    for (int s = 32; s >= 1; s >>= 1) {
        if (t < s) sred[t] += sred[t + s];
        __syncthreads();
    }
    {
        float invZ = 1.0f / sred[0];
        if (t < 64) {
            float aw = ex * invZ;
            saw[t] = aw;
            out_aw2[b * 64 + t]  = aw;
            out_cov2[b * 64 + t] = scov[t] + aw;
        }
    }
    __syncthreads();

    if (t < 96) {
        float c = 0.f;
        const float* ebp = sEnc + t;
#pragma unroll 8
        for (int e = 0; e < 64; e++) c = fmaf(saw[e], ebp[e * 96], c);
        out_ctx2[b * 96 + t] = c;
        so2[t]       = shnew[t];
        so2[96 + t]  = c;
    }
    __syncthreads();

    // =========== outproj ===========
#pragma unroll
    for (int k = 0; k < 3; k++) {
        int h = warp * 3 + k;
        const float* wr = W_pre + h * 192;
        float a = 0.f;
#pragma unroll
        for (int q = 0; q < 6; q++) {
            int j = lane + 32 * q;
            a = fmaf(so2[j], wr[j], a);
        }
#pragma unroll
        for (int s = 16; s > 0; s >>= 1) a += __shfl_down_sync(0xffffffffu, a, s);
        if (lane == 0) g_o[b * 96 + h] = tanhf(a + b_pre[h]);
    }
}

// =====================================================================
// K3: logits written straight into out buffer + per-block sumexp partials.
// 128 threads, 128 vocab rows per block, 250 blocks. sW in dynamic smem.
// =====================================================================
extern __shared__ float smem3[];

__global__ void logits_kernel(const float* __restrict__ W_out,
                              const float* __restrict__ b_out,
                              float* __restrict__ out_logp) {
    float* sW = smem3;                            // 128 * 97 (padded)
    __shared__ __align__(16) float sO[96 * 16];   // [k][b]
    __shared__ float red[128 * 17];
    int t = threadIdx.x;        // 128
    int v0 = blockIdx.x * 128;

    for (int idx = t; idx < 128 * 96; idx += 128) {
        int r = idx / 96;
        int k = idx - r * 96;
        sW[r * 97 + k] = W_out[(size_t)v0 * 96 + idx];
    }
    for (int idx = t; idx < 1536; idx += 128) {
        int k = idx >> 4, bb = idx & 15;
        sO[idx] = g_o[bb * 96 + k];
    }
    __syncthreads();

    float acc[16];
    float bo = b_out[v0 + t];
#pragma unroll
    for (int bb = 0; bb < 16; bb++) acc[bb] = bo;

    const float* wr = sW + t * 97;
#pragma unroll 4
    for (int k = 0; k < 96; k++) {
        float w = wr[k];
        const float4* o4 = (const float4*)(sO + k * 16);
#pragma unroll
        for (int q = 0; q < 4; q++) {
            float4 ov = o4[q];
            acc[q * 4 + 0] = fmaf(w, ov.x, acc[q * 4 + 0]);
            acc[q * 4 + 1] = fmaf(w, ov.y, acc[q * 4 + 1]);
            acc[q * 4 + 2] = fmaf(w, ov.z, acc[q * 4 + 2]);
            acc[q * 4 + 3] = fmaf(w, ov.w, acc[q * 4 + 3]);
        }
    }
#pragma unroll
    for (int bb = 0; bb < 16; bb++) {
        out_logp[bb * VOC + v0 + t] = acc[bb];
        red[t * 17 + bb] = expf(acc[bb]);
    }
    __syncthreads();
    for (int s = 64; s >= 1; s >>= 1) {
        if (t < s) {
#pragma unroll
            for (int bb = 0; bb < 16; bb++) red[t * 17 + bb] += red[(t + s) * 17 + bb];
        }
        __syncthreads();
    }
    if (t == 0) {
#pragma unroll
        for (int bb = 0; bb < 16; bb++) g_psum[blockIdx.x * 16 + bb] = red[bb];
    }
}

// =====================================================================
// K4: finalize — each block computes logZ[b] (tree over 250 psums) and
// subtracts it in place from its chunk of logits.
// grid = (63, 16), block = 512.
// =====================================================================
__global__ void finalize_kernel(float* __restrict__ out_logp) {
    __shared__ float sred[256];
    int t = threadIdx.x;        // 512
    int b = blockIdx.y;

    if (t < 256) sred[t] = (t < 250) ? g_psum[t * 16 + b] : 0.f;
    __syncthreads();
    for (int s = 128; s >= 1; s >>= 1) {
        if (t < s) sred[t] += sred[t + s];
        __syncthreads();
    }
    float logZ = logf(sred[0]);

    int v = blockIdx.x * 512 + t;
    if (v < VOC) {
        out_logp[b * VOC + v] = out_logp[b * VOC + v] - logZ;
    }
}

// =====================================================================
extern "C" void kernel_launch(void* const* d_in, const int* in_sizes, int n_in,
                              void* d_out, int out_size) {
    const float* enc      = (const float*)d_in[0];
    const int*   ids      = (const int*)d_in[1];
    const float* hidden   = (const float*)d_in[2];
    const float* coverage = (const float*)d_in[3];
    const float* emb      = (const float*)d_in[4];
    const float* W_dec    = (const float*)d_in[5];
    const float* b_dec    = (const float*)d_in[6];
    const float* attn_w   = (const float*)d_in[7];
    const float* attn_b   = (const float*)d_in[8];
    const float* cvg_w    = (const float*)d_in[9];
    const float* cvg_b    = (const float*)d_in[10];
    const float* v        = (const float*)d_in[11];
    const float* W_new    = (const float*)d_in[12];
    const float* b_new    = (const float*)d_in[13];
    const float* w_ih     = (const float*)d_in[14];
    const float* w_hh     = (const float*)d_in[15];
    const float* b_ih     = (const float*)d_in[16];
    const float* b_hh     = (const float*)d_in[17];
    const float* W_pre    = (const float*)d_in[18];
    const float* b_pre    = (const float*)d_in[19];
    const float* W_out    = (const float*)d_in[20];
    const float* b_out    = (const float*)d_in[21];

    float* out        = (float*)d_out;
    float* out_logp   = out;                       // 16*32000
    float* out_hidden = out + 512000;              // 1*16*96
    float* out_ctx2   = out + 513536;              // 16*96
    float* out_aw2    = out + 515072;              // 16*64
    float* out_cov2   = out + 516096;              // 16*64

    cudaFuncSetAttribute(enc_feat_kernel, cudaFuncAttributeMaxDynamicSharedMemorySize, 98304);
    cudaFuncSetAttribute(decoder_fused_kernel, cudaFuncAttributeMaxDynamicSharedMemorySize, 25600 * 4);
    cudaFuncSetAttribute(logits_kernel, cudaFuncAttributeMaxDynamicSharedMemorySize, 128 * 97 * 4);

    // K1: shared enc_feat (used by both attention phases)
    enc_feat_kernel<<<512, 128, 98304>>>(enc, attn_w, attn_b);
    // K2: fused attn1 + GRU + attn2 + outproj (per-batch blocks)
    decoder_fused_kernel<<<16, 1024, 25600 * 4>>>(
        enc, ids, hidden, coverage, emb, W_dec, b_dec, cvg_w, cvg_b, v,
        W_new, b_new, w_ih, w_hh, b_ih, b_hh, W_pre, b_pre,
        out_hidden, out_ctx2, out_aw2, out_cov2);
    // K3: logits -> out buffer + sumexp partials
    logits_kernel<<<VOC / 128, 128, 128 * 97 * 4>>>(W_out, b_out, out_logp);
    // K4: logZ + in-place log_softmax normalize
    finalize_kernel<<<dim3(63, 16), 512>>>(out_logp);
}

// round 4
// speedup vs baseline: 2.4807x; 1.1159x over previous
#include <cuda_runtime.h>
#include <math.h>

#define BATCH 16
#define ENCN  64
#define HDIM  96
#define EDIM  128
#define VOC   32000

typedef unsigned long long u64;

__device__ __forceinline__ u64 pack2(float x) {
    u64 r;
    asm("mov.b64 %0, {%1, %1};" : "=l"(r) : "r"(__float_as_uint(x)));
    return r;
}
__device__ __forceinline__ u64 fma2(u64 a, u64 b, u64 c) {
    u64 d;
    asm("fma.rn.f32x2 %0, %1, %2, %3;" : "=l"(d) : "l"(a), "l"(b), "l"(c));
    return d;
}
__device__ __forceinline__ void unpack2(u64 v, float& lo, float& hi) {
    unsigned int l, h;
    asm("mov.b64 {%0, %1}, %2;" : "=r"(l), "=r"(h) : "l"(v));
    lo = __uint_as_float(l);
    hi = __uint_as_float(h);
}

// ---------------- scratch ----------------
__device__ float g_ef0[BATCH * ENCN * HDIM];   // enc_feat partial (i 0..31, +bias)
__device__ float g_ef1[BATCH * ENCN * HDIM];   // enc_feat partial (i 32..63)
__device__ float g_o[BATCH * HDIM];
__device__ float g_psum[256 * BATCH];
__device__ float g_logZ[BATCH];

// =====================================================================
// K1: enc_feat partials. grid (512, 2): x = b*32 + o-pair, y = i-half.
// smem 48KB/block -> ~4 blocks/SM (16 warps) for latency hiding.
// 128 threads = 8 i-groups (4 ch each) x 16 w-threads; rotating packed
// (e,e) window; 6x fma.rn.f32x2 per u-step.
// =====================================================================
extern __shared__ float smem1[];

__global__ void enc_feat_kernel(const float* __restrict__ enc,
                                const float* __restrict__ attn_w,
                                const float* __restrict__ attn_b) {
    int b    = blockIdx.x >> 5;
    int gp   = blockIdx.x & 31;
    int half = blockIdx.y;          // 0 or 1
    int o0   = gp * 2;
    int i0   = half * 32;

    float* sE = smem1;                        // 32 * 192 floats
    u64*   sK = (u64*)(smem1 + 32 * 192);     // 32 * 96 packed (k_o0, k_o1)
    int tid = threadIdx.x;          // 128

    float4* sE4 = (float4*)sE;
    for (int i = tid; i < 32 * 192 / 4; i += 128) sE4[i] = make_float4(0.f, 0.f, 0.f, 0.f);
    __syncthreads();

    const float* eb = enc + (b * ENCN + i0) * HDIM;
    for (int idx = tid; idx < 32 * HDIM; idx += 128) {
        int i = idx / 96;
        int x = idx - i * 96;
        sE[i * 192 + 47 + x] = eb[idx];
    }
    const float* k0 = attn_w + (size_t)o0 * 589824 + (size_t)i0 * 9216 + 4512;
    const float* k1 = k0 + 589824;
    for (int idx = tid; idx < 32 * 96; idx += 128) {
        int i = idx / 96;
        int d = idx - i * 96;
        float2 kk = make_float2(k0[i * 9216 + d], k1[i * 9216 + d]);
        sK[idx] = *(u64*)&kk;
    }
    __syncthreads();

    int ig = tid >> 4;      // 0..7, 4 channels each
    int wt = tid & 15;
    int w0 = wt * 6;

    u64 acc[6] = {0ull, 0ull, 0ull, 0ull, 0ull, 0ull};

#pragma unroll 1
    for (int i = ig * 4; i < ig * 4 + 4; i++) {
        const float* Er = sE + i * 192 + w0;
        const u64*   Kr = sK + i * 96;
        u64 ep[6];
#pragma unroll
        for (int j = 0; j < 6; j++) ep[j] = pack2(Er[j]);
#pragma unroll 1
        for (int d = 0; d < 96; d += 6) {
#pragma unroll
            for (int u = 0; u < 6; u++) {
                u64 k2 = Kr[d + u];
#pragma unroll
                for (int j = 0; j < 6; j++) {
                    acc[j] = fma2(ep[(u + j) % 6], k2, acc[j]);
                }
                ep[u] = pack2(Er[d + u + 6]);
            }
        }
    }

    float a0[6], a1[6];
#pragma unroll
    for (int j = 0; j < 6; j++) unpack2(acc[j], a0[j], a1[j]);

    __syncthreads();
    float* red = smem1;
#pragma unroll
    for (int j = 0; j < 6; j++) {
        red[tid * 12 + j]     = a0[j];
        red[tid * 12 + 6 + j] = a1[j];
    }
    __syncthreads();
    for (int s = 64; s >= 16; s >>= 1) {
        if (tid < s) {
#pragma unroll
            for (int j = 0; j < 12; j++) red[tid * 12 + j] += red[(tid + s) * 12 + j];
        }
        __syncthreads();
    }
    if (tid < 16) {
        float* dst = half ? g_ef1 : g_ef0;
        float bb0 = half ? 0.f : attn_b[o0];
        float bb1 = half ? 0.f : attn_b[o0 + 1];
#pragma unroll
        for (int j = 0; j < 6; j++) {
            dst[(b * ENCN + o0) * 96 + tid * 6 + j]     = red[tid * 12 + j] + bb0;
            dst[(b * ENCN + o0 + 1) * 96 + tid * 6 + j] = red[tid * 12 + 6 + j] + bb1;
        }
    }
}

// =====================================================================
// K2: fully fused per-batch decoder: attn1 -> GRU -> attn2 -> outproj.
// grid=16 (one block per batch), block=1024 (32 warps).
// =====================================================================
extern __shared__ float smem2[];

__global__ void decoder_fused_kernel(const float* __restrict__ enc,
                                     const int* __restrict__ ids,
                                     const float* __restrict__ hidden,
                                     const float* __restrict__ coverage,
                                     const float* __restrict__ emb,
                                     const float* __restrict__ W_dec,
                                     const float* __restrict__ b_dec,
                                     const float* __restrict__ cvg_w,
                                     const float* __restrict__ cvg_b,
                                     const float* __restrict__ v,
                                     const float* __restrict__ W_new,
                                     const float* __restrict__ b_new,
                                     const float* __restrict__ w_ih,
                                     const float* __restrict__ w_hh,
                                     const float* __restrict__ b_ih,
                                     const float* __restrict__ b_hh,
                                     const float* __restrict__ W_pre,
                                     const float* __restrict__ b_pre,
                                     float* __restrict__ out_hidden,
                                     float* __restrict__ out_ctx2,
                                     float* __restrict__ out_aw2,
                                     float* __restrict__ out_cov2) {
    int b    = blockIdx.x;
    int t    = threadIdx.x;     // 1024
    int warp = t >> 5;
    int lane = t & 31;

    float* sWdec = smem2;               // 9216
    float* sC    = sWdec + 9216;        // 4096   C[e][i] = cvg_w[e,i,0,47]
    float* sEnc  = sC + 4096;           // 6144   enc[b]
    float* sEf   = sEnc + 6144;         // 6144   encfeat[b]

    __shared__ float sh[96], sv[96], scov[64], sdec[96], scvg[64], ss[64],
                     saw[64], sred[64], sctx[96], scat[224], sx[96],
                     sgi[288], sgh[288], shnew[96], so2[192];

    for (int i = t; i < 9216; i += 1024) sWdec[i] = W_dec[i];
    for (int i = t; i < 4096; i += 1024) {
        int e = i >> 6, ii = i & 63;
        sC[i] = cvg_w[e * 6144 + ii * 96 + 47];
    }
    for (int i = t; i < 6144; i += 1024) {
        sEnc[i] = enc[b * 6144 + i];
        sEf[i]  = g_ef0[b * 6144 + i] + g_ef1[b * 6144 + i];
    }
    if (t < 96) { sh[t] = hidden[b * 96 + t]; sv[t] = v[b * 96 + t]; }
    if (t < 64) scov[t] = coverage[b * 64 + t];
    __syncthreads();

    // =========== PHASE A: attention #1 ===========
#pragma unroll
    for (int k = 0; k < 3; k++) {
        int h = warp * 3 + k;
        const float* wr = sWdec + h * 96;
        float a = sh[lane] * wr[lane];
        a = fmaf(sh[lane + 32], wr[lane + 32], a);
        a = fmaf(sh[lane + 64], wr[lane + 64], a);
#pragma unroll
        for (int s = 16; s > 0; s >>= 1) a += __shfl_down_sync(0xffffffffu, a, s);
        if (lane == 0) sdec[h] = a + b_dec[h];
    }
#pragma unroll
    for (int k = 0; k < 2; k++) {
        int e = warp * 2 + k;
        const float* cw = sC + e * 64;
        float c = scov[lane] * cw[lane];
        c = fmaf(scov[lane + 32], cw[lane + 32], c);
#pragma unroll
        for (int s = 16; s > 0; s >>= 1) c += __shfl_down_sync(0xffffffffu, c, s);
        if (lane == 0) scvg[e] = c + cvg_b[e];
    }
    __syncthreads();

#pragma unroll
    for (int k = 0; k < 2; k++) {
        int e = warp * 2 + k;
        const float* ef = sEf + e * 96;
        float cg = scvg[e];
        float a = 0.f;
#pragma unroll
        for (int q = 0; q < 3; q++) {
            int h = lane + 32 * q;
            a = fmaf(tanhf(ef[h] + sdec[h] + cg), sv[h], a);
        }
#pragma unroll
        for (int s = 16; s > 0; s >>= 1) a += __shfl_down_sync(0xffffffffu, a, s);
        if (lane == 0) ss[e] = a;
    }
    __syncthreads();

    float ex = 0.f;
    if (t < 64) {
        float m = -1e30f;
#pragma unroll
        for (int e = 0; e < 64; e++) m = fmaxf(m, ss[e]);
        ex = expf(ss[t] - m);
        sred[t] = ex;
    }
    __syncthreads();
    for (int s = 32; s >= 1; s >>= 1) {
        if (t < s) sred[t] += sred[t + s];
        __syncthreads();
    }
    {
        float invZ = 1.0f / sred[0];
        if (t < 64) {
            float aw = ex * invZ;
            saw[t] = aw;
            scov[t] = scov[t] + aw;
        }
    }
    __syncthreads();

    if (t < 96) {
        float c = 0.f;
        const float* ebp = sEnc + t;
#pragma unroll 8
        for (int e = 0; e < 64; e++) c = fmaf(saw[e], ebp[e * 96], c);
        sctx[t] = c;
    }
    __syncthreads();

    // =========== GRU ===========
    {
        int id = ids[b];
        if (t < 224) scat[t] = (t < 128) ? emb[(size_t)id * 128 + t] : sctx[t - 128];
    }
    __syncthreads();

#pragma unroll
    for (int k = 0; k < 3; k++) {
        int h = warp * 3 + k;
        const float* wr = W_new + h * 224;
        float a = 0.f;
#pragma unroll
        for (int q = 0; q < 7; q++) {
            int j = lane + 32 * q;
            a = fmaf(scat[j], wr[j], a);
        }
#pragma unroll
        for (int s = 16; s > 0; s >>= 1) a += __shfl_down_sync(0xffffffffu, a, s);
        if (lane == 0) sx[h] = a + b_new[h];
    }
    __syncthreads();

#pragma unroll
    for (int k = 0; k < 18; k++) {
        int r = k * 32 + warp;
        bool is_gi = r < 288;
        int rr = is_gi ? r : r - 288;
        const float* wr  = (is_gi ? w_ih : w_hh) + rr * 96;
        const float* vec = is_gi ? sx : sh;
        float a = vec[lane] * wr[lane];
        a = fmaf(vec[lane + 32], wr[lane + 32], a);
        a = fmaf(vec[lane + 64], wr[lane + 64], a);
#pragma unroll
        for (int s = 16; s > 0; s >>= 1) a += __shfl_down_sync(0xffffffffu, a, s);
        if (lane == 0) {
            if (is_gi) sgi[rr] = a + b_ih[rr];
            else       sgh[rr] = a + b_hh[rr];
        }
    }
    __syncthreads();

    if (t < 96) {
        float r = 1.0f / (1.0f + expf(-(sgi[t] + sgh[t])));
        float z = 1.0f / (1.0f + expf(-(sgi[96 + t] + sgh[96 + t])));
        float n = tanhf(sgi[192 + t] + r * sgh[192 + t]);
        float hn = (1.0f - z) * n + z * sh[t];
        shnew[t] = hn;
        out_hidden[b * 96 + t] = hn;
    }
    __syncthreads();

    // =========== PHASE B: attention #2 ===========
#pragma unroll
    for (int k = 0; k < 3; k++) {
        int h = warp * 3 + k;
        const float* wr = sWdec + h * 96;
        float a = shnew[lane] * wr[lane];
        a = fmaf(shnew[lane + 32], wr[lane + 32], a);
        a = fmaf(shnew[lane + 64], wr[lane + 64], a);
#pragma unroll
        for (int s = 16; s > 0; s >>= 1) a += __shfl_down_sync(0xffffffffu, a, s);
        if (lane == 0) sdec[h] = a + b_dec[h];
    }
#pragma unroll
    for (int k = 0; k < 2; k++) {
        int e = warp * 2 + k;
        const float* cw = sC + e * 64;
        float c = scov[lane] * cw[lane];
        c = fmaf(scov[lane + 32], cw[lane + 32], c);
#pragma unroll
        for (int s = 16; s > 0; s >>= 1) c += __shfl_down_sync(0xffffffffu, c, s);
        if (lane == 0) scvg[e] = c + cvg_b[e];
    }
    __syncthreads();

#pragma unroll
    for (int k = 0; k < 2; k++) {
        int e = warp * 2 + k;
        const float* ef = sEf + e * 96;
        float cg = scvg[e];
        float a = 0.f;
#pragma unroll
        for (int q = 0; q < 3; q++) {
            int h = lane + 32 * q;
            a = fmaf(tanhf(ef[h] + sdec[h] + cg), sv[h], a);
        }
#pragma unroll
        for (int s = 16; s > 0; s >>= 1) a += __shfl_down_sync(0xffffffffu, a, s);
        if (lane == 0) ss[e] = a;
    }
    __syncthreads();

    ex = 0.f;
    if (t < 64) {
        float m = -1e30f;
#pragma unroll
        for (int e = 0; e < 64; e++) m = fmaxf(m, ss[e]);
        ex = expf(ss[t] - m);
        sred[t] = ex;
    }
    __syncthreads();
    for (int s = 32; s >= 1; s >>= 1) {
        if (t < s) sred[t] += sred[t + s];
        __syncthreads();
    }
    {
        float invZ = 1.0f / sred[0];
        if (t < 64) {
            float aw = ex * invZ;
            saw[t] = aw;
            out_aw2[b * 64 + t]  = aw;
            out_cov2[b * 64 + t] = scov[t] + aw;
        }
    }
    __syncthreads();

    if (t < 96) {
        float c = 0.f;
        const float* ebp = sEnc + t;
#pragma unroll 8
        for (int e = 0; e < 64; e++) c = fmaf(saw[e], ebp[e * 96], c);
        out_ctx2[b * 96 + t] = c;
        so2[t]       = shnew[t];
        so2[96 + t]  = c;
    }
    __syncthreads();

    // =========== outproj ===========
#pragma unroll
    for (int k = 0; k < 3; k++) {
        int h = warp * 3 + k;
        const float* wr = W_pre + h * 192;
        float a = 0.f;
#pragma unroll
        for (int q = 0; q < 6; q++) {
            int j = lane + 32 * q;
            a = fmaf(so2[j], wr[j], a);
        }
#pragma unroll
        for (int s = 16; s > 0; s >>= 1) a += __shfl_down_sync(0xffffffffu, a, s);
        if (lane == 0) g_o[b * 96 + h] = tanhf(a + b_pre[h]);
    }
}

// =====================================================================
// K3: logits -> out buffer + per-block sumexp partials (warp shfl).
// 256 threads, 256 vocab rows per block, 125 blocks.
// =====================================================================
extern __shared__ float smem3[];

__global__ void logits_kernel(const float* __restrict__ W_out,
                              const float* __restrict__ b_out,
                              float* __restrict__ out_logp) {
    float* sW = smem3;                            // 256 * 97 (padded)
    __shared__ __align__(16) float sO[96 * 16];   // [k][b]
    __shared__ float swred[8][16];
    int t = threadIdx.x;        // 256
    int warp = t >> 5, lane = t & 31;
    int v0 = blockIdx.x * 256;

    for (int idx = t; idx < 256 * 96; idx += 256) {
        int r = idx / 96;
        int k = idx - r * 96;
        sW[r * 97 + k] = W_out[(size_t)v0 * 96 + idx];
    }
    for (int idx = t; idx < 1536; idx += 256) {
        int k = idx >> 4, bb = idx & 15;
        sO[idx] = g_o[bb * 96 + k];
    }
    __syncthreads();

    float acc[16];
    float bo = b_out[v0 + t];
#pragma unroll
    for (int bb = 0; bb < 16; bb++) acc[bb] = bo;

    const float* wr = sW + t * 97;
#pragma unroll 4
    for (int k = 0; k < 96; k++) {
        float w = wr[k];
        const float4* o4 = (const float4*)(sO + k * 16);
#pragma unroll
        for (int q = 0; q < 4; q++) {
            float4 ov = o4[q];
            acc[q * 4 + 0] = fmaf(w, ov.x, acc[q * 4 + 0]);
            acc[q * 4 + 1] = fmaf(w, ov.y, acc[q * 4 + 1]);
            acc[q * 4 + 2] = fmaf(w, ov.z, acc[q * 4 + 2]);
            acc[q * 4 + 3] = fmaf(w, ov.w, acc[q * 4 + 3]);
        }
    }
#pragma unroll
    for (int bb = 0; bb < 16; bb++) {
        out_logp[bb * VOC + v0 + t] = acc[bb];
        acc[bb] = expf(acc[bb]);
    }
    // warp-level sumexp reduce for each batch
#pragma unroll
    for (int bb = 0; bb < 16; bb++) {
#pragma unroll
        for (int s = 16; s > 0; s >>= 1) acc[bb] += __shfl_down_sync(0xffffffffu, acc[bb], s);
    }
    if (lane == 0) {
#pragma unroll
        for (int bb = 0; bb < 16; bb++) swred[warp][bb] = acc[bb];
    }
    __syncthreads();
    if (t < 16) {
        float s = 0.f;
#pragma unroll
        for (int w = 0; w < 8; w++) s += swred[w][t];
        g_psum[blockIdx.x * 16 + t] = s;
    }
}

// K4: logZ (tiny, one block)
__global__ void logz_kernel() {
    int t = threadIdx.x;
    if (t < 16) {
        float s = 0.f;
        for (int blk = 0; blk < 125; blk++) s += g_psum[blk * 16 + t];
        g_logZ[t] = logf(s);
    }
}

// K5: streaming in-place subtract, float4. grid (32, 16), block 256.
__global__ void finalize_kernel(float* __restrict__ out_logp) {
    int b = blockIdx.y;
    float lz = g_logZ[b];
    int i = blockIdx.x * 256 + threadIdx.x;      // float4 index, 8000 per batch
    if (i < 8000) {
        float4* p = (float4*)(out_logp + (size_t)b * VOC);
        float4 v = p[i];
        v.x -= lz; v.y -= lz; v.z -= lz; v.w -= lz;
        p[i] = v;
    }
}

// =====================================================================
extern "C" void kernel_launch(void* const* d_in, const int* in_sizes, int n_in,
                              void* d_out, int out_size) {
    const float* enc      = (const float*)d_in[0];
    const int*   ids      = (const int*)d_in[1];
    const float* hidden   = (const float*)d_in[2];
    const float* coverage = (const float*)d_in[3];
    const float* emb      = (const float*)d_in[4];
    const float* W_dec    = (const float*)d_in[5];
    const float* b_dec    = (const float*)d_in[6];
    const float* attn_w   = (const float*)d_in[7];
    const float* attn_b   = (const float*)d_in[8];
    const float* cvg_w    = (const float*)d_in[9];
    const float* cvg_b    = (const float*)d_in[10];
    const float* v        = (const float*)d_in[11];
    const float* W_new    = (const float*)d_in[12];
    const float* b_new    = (const float*)d_in[13];
    const float* w_ih     = (const float*)d_in[14];
    const float* w_hh     = (const float*)d_in[15];
    const float* b_ih     = (const float*)d_in[16];
    const float* b_hh     = (const float*)d_in[17];
    const float* W_pre    = (const float*)d_in[18];
    const float* b_pre    = (const float*)d_in[19];
    const float* W_out    = (const float*)d_in[20];
    const float* b_out    = (const float*)d_in[21];

    float* out        = (float*)d_out;
    float* out_logp   = out;                       // 16*32000
    float* out_hidden = out + 512000;              // 1*16*96
    float* out_ctx2   = out + 513536;              // 16*96
    float* out_aw2    = out + 515072;              // 16*64
    float* out_cov2   = out + 516096;              // 16*64

    cudaFuncSetAttribute(enc_feat_kernel, cudaFuncAttributeMaxDynamicSharedMemorySize, 49152);
    cudaFuncSetAttribute(decoder_fused_kernel, cudaFuncAttributeMaxDynamicSharedMemorySize, 25600 * 4);
    cudaFuncSetAttribute(logits_kernel, cudaFuncAttributeMaxDynamicSharedMemorySize, 256 * 97 * 4);

    // K1: enc_feat partials (i-split for occupancy)
    enc_feat_kernel<<<dim3(512, 2), 128, 49152>>>(enc, attn_w, attn_b);
    // K2: fused attn1 + GRU + attn2 + outproj
    decoder_fused_kernel<<<16, 1024, 25600 * 4>>>(
        enc, ids, hidden, coverage, emb, W_dec, b_dec, cvg_w, cvg_b, v,
        W_new, b_new, w_ih, w_hh, b_ih, b_hh, W_pre, b_pre,
        out_hidden, out_ctx2, out_aw2, out_cov2);
    // K3: logits + sumexp partials
    logits_kernel<<<VOC / 256, 256, 256 * 97 * 4>>>(W_out, b_out, out_logp);
    // K4: logZ
    logz_kernel<<<1, 32>>>();
    // K5: in-place normalize
    finalize_kernel<<<dim3(32, 16), 256>>>(out_logp);
}

// round 5
// speedup vs baseline: 2.6414x; 1.0648x over previous
#include <cuda_runtime.h>
#include <math.h>

#define BATCH 16
#define ENCN  64
#define HDIM  96
#define EDIM  128
#define VOC   32000

typedef unsigned long long u64;

__device__ __forceinline__ u64 pack2(float x) {
    u64 r;
    asm("mov.b64 %0, {%1, %1};" : "=l"(r) : "r"(__float_as_uint(x)));
    return r;
}
__device__ __forceinline__ u64 fma2(u64 a, u64 b, u64 c) {
    u64 d;
    asm("fma.rn.f32x2 %0, %1, %2, %3;" : "=l"(d) : "l"(a), "l"(b), "l"(c));
    return d;
}
__device__ __forceinline__ void unpack2(u64 v, float& lo, float& hi) {
    unsigned int l, h;
    asm("mov.b64 {%0, %1}, %2;" : "=r"(l), "=r"(h) : "l"(v));
    lo = __uint_as_float(l);
    hi = __uint_as_float(h);
}

// ---------------- scratch ----------------
__device__ float g_ef0[BATCH * ENCN * HDIM];   // enc_feat partial (i 0..31, +bias)
__device__ float g_ef1[BATCH * ENCN * HDIM];   // enc_feat partial (i 32..63)
__device__ float g_o[BATCH * HDIM];
__device__ float g_psum[256 * BATCH];

// =====================================================================
// K1: enc_feat partials. grid (512, 2): x = b*32 + o-pair, y = i-half.
// =====================================================================
extern __shared__ float smem1[];

__global__ void enc_feat_kernel(const float* __restrict__ enc,
                                const float* __restrict__ attn_w,
                                const float* __restrict__ attn_b) {
    int b    = blockIdx.x >> 5;
    int gp   = blockIdx.x & 31;
    int half = blockIdx.y;
    int o0   = gp * 2;
    int i0   = half * 32;

    float* sE = smem1;                        // 32 * 192 floats
    u64*   sK = (u64*)(smem1 + 32 * 192);     // 32 * 96 packed (k_o0, k_o1)
    int tid = threadIdx.x;          // 128

    float4* sE4 = (float4*)sE;
    for (int i = tid; i < 32 * 192 / 4; i += 128) sE4[i] = make_float4(0.f, 0.f, 0.f, 0.f);
    __syncthreads();

    const float* eb = enc + (b * ENCN + i0) * HDIM;
    for (int idx = tid; idx < 32 * HDIM; idx += 128) {
        int i = idx / 96;
        int x = idx - i * 96;
        sE[i * 192 + 47 + x] = eb[idx];
    }
    const float* k0 = attn_w + (size_t)o0 * 589824 + (size_t)i0 * 9216 + 4512;
    const float* k1 = k0 + 589824;
    for (int idx = tid; idx < 32 * 96; idx += 128) {
        int i = idx / 96;
        int d = idx - i * 96;
        float2 kk = make_float2(k0[i * 9216 + d], k1[i * 9216 + d]);
        sK[idx] = *(u64*)&kk;
    }
    __syncthreads();

    int ig = tid >> 4;      // 0..7, 4 channels each
    int wt = tid & 15;
    int w0 = wt * 6;

    u64 acc[6] = {0ull, 0ull, 0ull, 0ull, 0ull, 0ull};

#pragma unroll 1
    for (int i = ig * 4; i < ig * 4 + 4; i++) {
        const float* Er = sE + i * 192 + w0;
        const u64*   Kr = sK + i * 96;
        u64 ep[6];
#pragma unroll
        for (int j = 0; j < 6; j++) ep[j] = pack2(Er[j]);
#pragma unroll 1
        for (int d = 0; d < 96; d += 6) {
#pragma unroll
            for (int u = 0; u < 6; u++) {
                u64 k2 = Kr[d + u];
#pragma unroll
                for (int j = 0; j < 6; j++) {
                    acc[j] = fma2(ep[(u + j) % 6], k2, acc[j]);
                }
                ep[u] = pack2(Er[d + u + 6]);
            }
        }
    }

    float a0[6], a1[6];
#pragma unroll
    for (int j = 0; j < 6; j++) unpack2(acc[j], a0[j], a1[j]);

    __syncthreads();
    float* red = smem1;
#pragma unroll
    for (int j = 0; j < 6; j++) {
        red[tid * 12 + j]     = a0[j];
        red[tid * 12 + 6 + j] = a1[j];
    }
    __syncthreads();
    for (int s = 64; s >= 16; s >>= 1) {
        if (tid < s) {
#pragma unroll
            for (int j = 0; j < 12; j++) red[tid * 12 + j] += red[(tid + s) * 12 + j];
        }
        __syncthreads();
    }
    if (tid < 16) {
        float* dst = half ? g_ef1 : g_ef0;
        float bb0 = half ? 0.f : attn_b[o0];
        float bb1 = half ? 0.f : attn_b[o0 + 1];
#pragma unroll
        for (int j = 0; j < 6; j++) {
            dst[(b * ENCN + o0) * 96 + tid * 6 + j]     = red[tid * 12 + j] + bb0;
            dst[(b * ENCN + o0 + 1) * 96 + tid * 6 + j] = red[tid * 12 + 6 + j] + bb1;
        }
    }
}

// =====================================================================
// K2: fully fused per-batch decoder: attn1 -> GRU -> attn2 -> outproj.
// grid=16 (one block per batch), block=1024 (32 warps).
// =====================================================================
extern __shared__ float smem2[];

__global__ void decoder_fused_kernel(const float* __restrict__ enc,
                                     const int* __restrict__ ids,
                                     const float* __restrict__ hidden,
                                     const float* __restrict__ coverage,
                                     const float* __restrict__ emb,
                                     const float* __restrict__ W_dec,
                                     const float* __restrict__ b_dec,
                                     const float* __restrict__ cvg_w,
                                     const float* __restrict__ cvg_b,
                                     const float* __restrict__ v,
                                     const float* __restrict__ W_new,
                                     const float* __restrict__ b_new,
                                     const float* __restrict__ w_ih,
                                     const float* __restrict__ w_hh,
                                     const float* __restrict__ b_ih,
                                     const float* __restrict__ b_hh,
                                     const float* __restrict__ W_pre,
                                     const float* __restrict__ b_pre,
                                     float* __restrict__ out_hidden,
                                     float* __restrict__ out_ctx2,
                                     float* __restrict__ out_aw2,
                                     float* __restrict__ out_cov2) {
    int b    = blockIdx.x;
    int t    = threadIdx.x;     // 1024
    int warp = t >> 5;
    int lane = t & 31;

    float* sWdec = smem2;               // 9216
    float* sC    = sWdec + 9216;        // 4096   C[e][i] = cvg_w[e,i,0,47]
    float* sEnc  = sC + 4096;           // 6144   enc[b]
    float* sEf   = sEnc + 6144;         // 6144   encfeat[b]

    __shared__ float sh[96], sv[96], scov[64], sdec[96], scvg[64], ss[64],
                     saw[64], sred[64], sctx[96], scat[224], sx[96],
                     sgi[288], sgh[288], shnew[96], so2[192];

    for (int i = t; i < 9216; i += 1024) sWdec[i] = W_dec[i];
    for (int i = t; i < 4096; i += 1024) {
        int e = i >> 6, ii = i & 63;
        sC[i] = cvg_w[e * 6144 + ii * 96 + 47];
    }
    for (int i = t; i < 6144; i += 1024) {
        sEnc[i] = enc[b * 6144 + i];
        sEf[i]  = g_ef0[b * 6144 + i] + g_ef1[b * 6144 + i];
    }
    if (t < 96) { sh[t] = hidden[b * 96 + t]; sv[t] = v[b * 96 + t]; }
    if (t < 64) scov[t] = coverage[b * 64 + t];
    __syncthreads();

    // =========== PHASE A: attention #1 ===========
#pragma unroll
    for (int k = 0; k < 3; k++) {
        int h = warp * 3 + k;
        const float* wr = sWdec + h * 96;
        float a = sh[lane] * wr[lane];
        a = fmaf(sh[lane + 32], wr[lane + 32], a);
        a = fmaf(sh[lane + 64], wr[lane + 64], a);
#pragma unroll
        for (int s = 16; s > 0; s >>= 1) a += __shfl_down_sync(0xffffffffu, a, s);
        if (lane == 0) sdec[h] = a + b_dec[h];
    }
#pragma unroll
    for (int k = 0; k < 2; k++) {
        int e = warp * 2 + k;
        const float* cw = sC + e * 64;
        float c = scov[lane] * cw[lane];
        c = fmaf(scov[lane + 32], cw[lane + 32], c);
#pragma unroll
        for (int s = 16; s > 0; s >>= 1) c += __shfl_down_sync(0xffffffffu, c, s);
        if (lane == 0) scvg[e] = c + cvg_b[e];
    }
    __syncthreads();

#pragma unroll
    for (int k = 0; k < 2; k++) {
        int e = warp * 2 + k;
        const float* ef = sEf + e * 96;
        float cg = scvg[e];
        float a = 0.f;
#pragma unroll
        for (int q = 0; q < 3; q++) {
            int h = lane + 32 * q;
            a = fmaf(tanhf(ef[h] + sdec[h] + cg), sv[h], a);
        }
#pragma unroll
        for (int s = 16; s > 0; s >>= 1) a += __shfl_down_sync(0xffffffffu, a, s);
        if (lane == 0) ss[e] = a;
    }
    __syncthreads();

    float ex = 0.f;
    if (t < 64) {
        float m = -1e30f;
#pragma unroll
        for (int e = 0; e < 64; e++) m = fmaxf(m, ss[e]);
        ex = expf(ss[t] - m);
        sred[t] = ex;
    }
    __syncthreads();
    for (int s = 32; s >= 1; s >>= 1) {
        if (t < s) sred[t] += sred[t + s];
        __syncthreads();
    }
    {
        float invZ = 1.0f / sred[0];
        if (t < 64) {
            float aw = ex * invZ;
            saw[t] = aw;
            scov[t] = scov[t] + aw;
        }
    }
    __syncthreads();

    if (t < 96) {
        float c = 0.f;
        const float* ebp = sEnc + t;
#pragma unroll 8
        for (int e = 0; e < 64; e++) c = fmaf(saw[e], ebp[e * 96], c);
        sctx[t] = c;
    }
    __syncthreads();

    // =========== GRU ===========
    {
        int id = ids[b];
        if (t < 224) scat[t] = (t < 128) ? emb[(size_t)id * 128 + t] : sctx[t - 128];
    }
    __syncthreads();

#pragma unroll
    for (int k = 0; k < 3; k++) {
        int h = warp * 3 + k;
        const float* wr = W_new + h * 224;
        float a = 0.f;
#pragma unroll
        for (int q = 0; q < 7; q++) {
            int j = lane + 32 * q;
            a = fmaf(scat[j], wr[j], a);
        }
#pragma unroll
        for (int s = 16; s > 0; s >>= 1) a += __shfl_down_sync(0xffffffffu, a, s);
        if (lane == 0) sx[h] = a + b_new[h];
    }
    __syncthreads();

#pragma unroll
    for (int k = 0; k < 18; k++) {
        int r = k * 32 + warp;
        bool is_gi = r < 288;
        int rr = is_gi ? r : r - 288;
        const float* wr  = (is_gi ? w_ih : w_hh) + rr * 96;
        const float* vec = is_gi ? sx : sh;
        float a = vec[lane] * wr[lane];
        a = fmaf(vec[lane + 32], wr[lane + 32], a);
        a = fmaf(vec[lane + 64], wr[lane + 64], a);
#pragma unroll
        for (int s = 16; s > 0; s >>= 1) a += __shfl_down_sync(0xffffffffu, a, s);
        if (lane == 0) {
            if (is_gi) sgi[rr] = a + b_ih[rr];
            else       sgh[rr] = a + b_hh[rr];
        }
    }
    __syncthreads();

    if (t < 96) {
        float r = 1.0f / (1.0f + expf(-(sgi[t] + sgh[t])));
        float z = 1.0f / (1.0f + expf(-(sgi[96 + t] + sgh[96 + t])));
        float n = tanhf(sgi[192 + t] + r * sgh[192 + t]);
        float hn = (1.0f - z) * n + z * sh[t];
        shnew[t] = hn;
        out_hidden[b * 96 + t] = hn;
    }
    __syncthreads();

    // =========== PHASE B: attention #2 ===========
#pragma unroll
    for (int k = 0; k < 3; k++) {
        int h = warp * 3 + k;
        const float* wr = sWdec + h * 96;
        float a = shnew[lane] * wr[lane];
        a = fmaf(shnew[lane + 32], wr[lane + 32], a);
        a = fmaf(shnew[lane + 64], wr[lane + 64], a);
#pragma unroll
        for (int s = 16; s > 0; s >>= 1) a += __shfl_down_sync(0xffffffffu, a, s);
        if (lane == 0) sdec[h] = a + b_dec[h];
    }
#pragma unroll
    for (int k = 0; k < 2; k++) {
        int e = warp * 2 + k;
        const float* cw = sC + e * 64;
        float c = scov[lane] * cw[lane];
        c = fmaf(scov[lane + 32], cw[lane + 32], c);
#pragma unroll
        for (int s = 16; s > 0; s >>= 1) c += __shfl_down_sync(0xffffffffu, c, s);
        if (lane == 0) scvg[e] = c + cvg_b[e];
    }
    __syncthreads();

#pragma unroll
    for (int k = 0; k < 2; k++) {
        int e = warp * 2 + k;
        const float* ef = sEf + e * 96;
        float cg = scvg[e];
        float a = 0.f;
#pragma unroll
        for (int q = 0; q < 3; q++) {
            int h = lane + 32 * q;
            a = fmaf(tanhf(ef[h] + sdec[h] + cg), sv[h], a);
        }
#pragma unroll
        for (int s = 16; s > 0; s >>= 1) a += __shfl_down_sync(0xffffffffu, a, s);
        if (lane == 0) ss[e] = a;
    }
    __syncthreads();

    ex = 0.f;
    if (t < 64) {
        float m = -1e30f;
#pragma unroll
        for (int e = 0; e < 64; e++) m = fmaxf(m, ss[e]);
        ex = expf(ss[t] - m);
        sred[t] = ex;
    }
    __syncthreads();
    for (int s = 32; s >= 1; s >>= 1) {
        if (t < s) sred[t] += sred[t + s];
        __syncthreads();
    }
    {
        float invZ = 1.0f / sred[0];
        if (t < 64) {
            float aw = ex * invZ;
            saw[t] = aw;
            out_aw2[b * 64 + t]  = aw;
            out_cov2[b * 64 + t] = scov[t] + aw;
        }
    }
    __syncthreads();

    if (t < 96) {
        float c = 0.f;
        const float* ebp = sEnc + t;
#pragma unroll 8
        for (int e = 0; e < 64; e++) c = fmaf(saw[e], ebp[e * 96], c);
        out_ctx2[b * 96 + t] = c;
        so2[t]       = shnew[t];
        so2[96 + t]  = c;
    }
    __syncthreads();

    // =========== outproj ===========
#pragma unroll
    for (int k = 0; k < 3; k++) {
        int h = warp * 3 + k;
        const float* wr = W_pre + h * 192;
        float a = 0.f;
#pragma unroll
        for (int q = 0; q < 6; q++) {
            int j = lane + 32 * q;
            a = fmaf(so2[j], wr[j], a);
        }
#pragma unroll
        for (int s = 16; s > 0; s >>= 1) a += __shfl_down_sync(0xffffffffu, a, s);
        if (lane == 0) g_o[b * 96 + h] = tanhf(a + b_pre[h]);
    }
}

// =====================================================================
// K3: logits via f32x2 (8 packed batch-pair accumulators).
// 250 blocks x 128 threads; 128 vocab rows per block.
// =====================================================================
extern __shared__ float smem3[];

__global__ void logits_kernel(const float* __restrict__ W_out,
                              const float* __restrict__ b_out,
                              float* __restrict__ out_logp) {
    float* sW = smem3;                               // 128 * 97 (padded)
    __shared__ __align__(16) u64 sO2[96 * 8];        // [k][bpair]
    __shared__ float swred[4][16];
    int t = threadIdx.x;        // 128
    int warp = t >> 5, lane = t & 31;
    int v0 = blockIdx.x * 128;

    // stage W rows: float4 gmem loads, scalar stores into padded smem
    {
        const float4* src = (const float4*)(W_out + (size_t)v0 * 96);
        for (int idx = t; idx < 128 * 24; idx += 128) {
            int r = idx / 24;
            int k4 = idx - r * 24;
            float4 w4 = src[r * 24 + k4];
            float* dst = sW + r * 97 + k4 * 4;
            dst[0] = w4.x; dst[1] = w4.y; dst[2] = w4.z; dst[3] = w4.w;
        }
    }
    for (int idx = t; idx < 96 * 8; idx += 128) {
        int k = idx >> 3, q = idx & 7;
        float2 oo = make_float2(g_o[(2 * q) * 96 + k], g_o[(2 * q + 1) * 96 + k]);
        sO2[idx] = *(u64*)&oo;
    }
    __syncthreads();

    u64 acc2[8] = {0ull, 0ull, 0ull, 0ull, 0ull, 0ull, 0ull, 0ull};
    const float* wr = sW + t * 97;
#pragma unroll 4
    for (int k = 0; k < 96; k++) {
        u64 wp = pack2(wr[k]);
        const u64* o2 = sO2 + k * 8;
#pragma unroll
        for (int q = 0; q < 8; q++) acc2[q] = fma2(wp, o2[q], acc2[q]);
    }

    float acc[16];
#pragma unroll
    for (int q = 0; q < 8; q++) unpack2(acc2[q], acc[2 * q], acc[2 * q + 1]);

    float bo = b_out[v0 + t];
#pragma unroll
    for (int bb = 0; bb < 16; bb++) {
        acc[bb] += bo;
        out_logp[bb * VOC + v0 + t] = acc[bb];
        acc[bb] = expf(acc[bb]);
    }
#pragma unroll
    for (int bb = 0; bb < 16; bb++) {
#pragma unroll
        for (int s = 16; s > 0; s >>= 1) acc[bb] += __shfl_down_sync(0xffffffffu, acc[bb], s);
    }
    if (lane == 0) {
#pragma unroll
        for (int bb = 0; bb < 16; bb++) swred[warp][bb] = acc[bb];
    }
    __syncthreads();
    if (t < 16) {
        float s = swred[0][t] + swred[1][t] + swred[2][t] + swred[3][t];
        g_psum[blockIdx.x * 16 + t] = s;
    }
}

// =====================================================================
// K4: finalize — each block cooperatively computes logZ[b] from the 250
// psums (L2-hot), then float4 in-place subtract. grid (32, 16), block 256.
// =====================================================================
__global__ void finalize_kernel(float* __restrict__ out_logp) {
    __shared__ float sred[256];
    int t = threadIdx.x;        // 256
    int b = blockIdx.y;

    sred[t] = (t < 250) ? g_psum[t * 16 + b] : 0.f;
    __syncthreads();
#pragma unroll
    for (int s = 128; s >= 1; s >>= 1) {
        if (t < s) sred[t] += sred[t + s];
        __syncthreads();
    }
    float lz = logf(sred[0]);

    int i = blockIdx.x * 256 + t;               // float4 index, 8000 per batch
    if (i < 8000) {
        float4* p = (float4*)(out_logp + (size_t)b * VOC);
        float4 v = p[i];
        v.x -= lz; v.y -= lz; v.z -= lz; v.w -= lz;
        p[i] = v;
    }
}

// =====================================================================
extern "C" void kernel_launch(void* const* d_in, const int* in_sizes, int n_in,
                              void* d_out, int out_size) {
    const float* enc      = (const float*)d_in[0];
    const int*   ids      = (const int*)d_in[1];
    const float* hidden   = (const float*)d_in[2];
    const float* coverage = (const float*)d_in[3];
    const float* emb      = (const float*)d_in[4];
    const float* W_dec    = (const float*)d_in[5];
    const float* b_dec    = (const float*)d_in[6];
    const float* attn_w   = (const float*)d_in[7];
    const float* attn_b   = (const float*)d_in[8];
    const float* cvg_w    = (const float*)d_in[9];
    const float* cvg_b    = (const float*)d_in[10];
    const float* v        = (const float*)d_in[11];
    const float* W_new    = (const float*)d_in[12];
    const float* b_new    = (const float*)d_in[13];
    const float* w_ih     = (const float*)d_in[14];
    const float* w_hh     = (const float*)d_in[15];
    const float* b_ih     = (const float*)d_in[16];
    const float* b_hh     = (const float*)d_in[17];
    const float* W_pre    = (const float*)d_in[18];
    const float* b_pre    = (const float*)d_in[19];
    const float* W_out    = (const float*)d_in[20];
    const float* b_out    = (const float*)d_in[21];

    float* out        = (float*)d_out;
    float* out_logp   = out;                       // 16*32000
    float* out_hidden = out + 512000;              // 1*16*96
    float* out_ctx2   = out + 513536;              // 16*96
    float* out_aw2    = out + 515072;              // 16*64
    float* out_cov2   = out + 516096;              // 16*64

    cudaFuncSetAttribute(enc_feat_kernel, cudaFuncAttributeMaxDynamicSharedMemorySize, 49152);
    cudaFuncSetAttribute(decoder_fused_kernel, cudaFuncAttributeMaxDynamicSharedMemorySize, 25600 * 4);
    cudaFuncSetAttribute(logits_kernel, cudaFuncAttributeMaxDynamicSharedMemorySize, 128 * 97 * 4);

    // K1: enc_feat partials (i-split for occupancy)
    enc_feat_kernel<<<dim3(512, 2), 128, 49152>>>(enc, attn_w, attn_b);
    // K2: fused attn1 + GRU + attn2 + outproj
    decoder_fused_kernel<<<16, 1024, 25600 * 4>>>(
        enc, ids, hidden, coverage, emb, W_dec, b_dec, cvg_w, cvg_b, v,
        W_new, b_new, w_ih, w_hh, b_ih, b_hh, W_pre, b_pre,
        out_hidden, out_ctx2, out_aw2, out_cov2);
    // K3: logits (f32x2) + sumexp partials
    logits_kernel<<<250, 128, 128 * 97 * 4>>>(W_out, b_out, out_logp);
    // K4: logZ + in-place normalize (fused)
    finalize_kernel<<<dim3(32, 16), 256>>>(out_logp);
}